// round 1
// baseline (speedup 1.0000x reference)
#include <cuda_runtime.h>
#include <math.h>

#define BATCH 16
#define CCH   512
#define NSP   4096
#define NGRP  16

// Scratch (device globals: allocation-free per harness rules)
__device__ float g_xn [(size_t)BATCH * CCH * NSP];        // normed input (also residual)
__device__ float g_kv [(size_t)BATCH * 2 * CCH * NSP];    // kv conv output; k half softmaxed in place
__device__ float g_q  [(size_t)BATCH * CCH * NSP];        // q = channel-softmax(k); later reused as gelu(gn2(out))
__device__ float g_ctx[(size_t)BATCH * CCH * CCH];        // per-batch C x C context
__device__ float g_o1 [(size_t)BATCH * CCH * NSP];        // attention output

// ---------------------------------------------------------------------------
// GroupNorm (optionally fused exact GELU). One block per (batch, group).
// Group = 32 channels * 4096 spatial = 131072 contiguous floats.
// ---------------------------------------------------------------------------
__global__ void gn_kernel(const float* __restrict__ x, const float* __restrict__ w,
                          const float* __restrict__ b, float* __restrict__ y, int gelu)
{
    const int GE = (CCH / NGRP) * NSP;  // 131072
    size_t base = (size_t)blockIdx.x * GE;
    int tid = threadIdx.x;

    float s = 0.f, s2 = 0.f;
    for (int i = tid; i < GE; i += 256) {
        float v = x[base + i];
        s += v; s2 += v * v;
    }
    __shared__ float sh1[256], sh2[256];
    sh1[tid] = s; sh2[tid] = s2;
    __syncthreads();
    for (int o = 128; o > 0; o >>= 1) {
        if (tid < o) { sh1[tid] += sh1[tid + o]; sh2[tid] += sh2[tid + o]; }
        __syncthreads();
    }
    float mean = sh1[0] / (float)GE;
    float var  = sh2[0] / (float)GE - mean * mean;
    float inv  = rsqrtf(var + 1e-5f);

    int cbase = (blockIdx.x & (NGRP - 1)) << 5;  // group * 32
    for (int i = tid; i < GE; i += 256) {
        int c = cbase + (i >> 12);  // i / 4096
        float v = (x[base + i] - mean) * inv * w[c] + b[c];
        if (gelu) v = 0.5f * v * (1.0f + erff(v * 0.70710678118654752f));
        y[base + i] = v;
    }
}

// ---------------------------------------------------------------------------
// Channel softmax: q[b,c,n] = softmax_c(k[b,c,n]) * scale.
// k lives in first half of kv buffer. One thread per spatial position.
// ---------------------------------------------------------------------------
__global__ void softmax_ch(const float* __restrict__ kv, float* __restrict__ q, float scale)
{
    int b = blockIdx.y;
    int n = blockIdx.x * blockDim.x + threadIdx.x;
    const float* kp = kv + (size_t)b * 2 * CCH * NSP + n;

    float m = -1e30f, s = 0.f;
    for (int c = 0; c < CCH; c++) {
        float v = kp[(size_t)c * NSP];
        if (v > m) { s = s * expf(m - v) + 1.0f; m = v; }
        else       { s += expf(v - m); }
    }
    float inv = scale / s;
    float* qp = q + (size_t)b * CCH * NSP + n;
    for (int c = 0; c < CCH; c++)
        qp[(size_t)c * NSP] = expf(kp[(size_t)c * NSP] - m) * inv;
}

// ---------------------------------------------------------------------------
// Spatial softmax, in-place on k half of kv. One block per (batch, channel) row.
// ---------------------------------------------------------------------------
__global__ void softmax_sp(float* __restrict__ kv)
{
    int b = blockIdx.x >> 9;         // / 512
    int c = blockIdx.x & (CCH - 1);
    float* p = kv + (size_t)b * 2 * CCH * NSP + (size_t)c * NSP;
    int tid = threadIdx.x;
    __shared__ float sh[256];

    float m = -1e30f;
    for (int i = tid; i < NSP; i += 256) m = fmaxf(m, p[i]);
    sh[tid] = m; __syncthreads();
    for (int o = 128; o > 0; o >>= 1) {
        if (tid < o) sh[tid] = fmaxf(sh[tid], sh[tid + o]);
        __syncthreads();
    }
    m = sh[0]; __syncthreads();

    float s = 0.f;
    for (int i = tid; i < NSP; i += 256) s += expf(p[i] - m);
    sh[tid] = s; __syncthreads();
    for (int o = 128; o > 0; o >>= 1) {
        if (tid < o) sh[tid] += sh[tid + o];
        __syncthreads();
    }
    float inv = 1.0f / sh[0];
    for (int i = tid; i < NSP; i += 256) p[i] = expf(p[i] - m) * inv;
}

// ---------------------------------------------------------------------------
// Batched fp32 GEMM: C[m,n] = sum_k A[m,k]*B[k,n] (+bias[m]) (+res[m,n])
// TA: A stored K-major (A_mem[k*lda+m]); TB: B stored N-major (B_mem[n*ldb+k]).
// 64x64 tile, BK=16, 256 threads, 4x4 per-thread micro-tile. Dims assumed
// divisible by 64/16 (true for all four GEMMs here).
// ---------------------------------------------------------------------------
template <bool TA, bool TB, bool HAS_BIAS, bool HAS_RES>
__global__ void gemm64(const float* __restrict__ A, const float* __restrict__ B,
                       float* __restrict__ C, const float* __restrict__ bias,
                       const float* __restrict__ res,
                       int M, int N, int K, int lda, int ldb, int ldc,
                       size_t sA, size_t sB, size_t sC, size_t sR)
{
    A += (size_t)blockIdx.z * sA;
    B += (size_t)blockIdx.z * sB;
    C += (size_t)blockIdx.z * sC;
    if (HAS_RES) res += (size_t)blockIdx.z * sR;

    __shared__ float As[16][68];  // padded: kills 16-way STS conflicts
    __shared__ float Bs[16][68];

    int tid = threadIdx.x;
    int tx = tid & 15, ty = tid >> 4;
    int m0 = blockIdx.y * 64, n0 = blockIdx.x * 64;

    float acc[4][4] = {};

    for (int k0 = 0; k0 < K; k0 += 16) {
#pragma unroll
        for (int i = 0; i < 4; i++) {
            int idx = i * 256 + tid;
            if (TA) { int m = idx & 63, k = idx >> 6; As[k][m] = A[(size_t)(k0 + k) * lda + m0 + m]; }
            else    { int k = idx & 15, m = idx >> 4; As[k][m] = A[(size_t)(m0 + m) * lda + k0 + k]; }
            if (TB) { int k = idx & 15, n = idx >> 4; Bs[k][n] = B[(size_t)(n0 + n) * ldb + k0 + k]; }
            else    { int n = idx & 63, k = idx >> 6; Bs[k][n] = B[(size_t)(k0 + k) * ldb + n0 + n]; }
        }
        __syncthreads();
#pragma unroll
        for (int kk = 0; kk < 16; kk++) {
            float a[4], bb[4];
#pragma unroll
            for (int i = 0; i < 4; i++) a[i]  = As[kk][ty * 4 + i];
#pragma unroll
            for (int j = 0; j < 4; j++) bb[j] = Bs[kk][tx * 4 + j];
#pragma unroll
            for (int i = 0; i < 4; i++)
#pragma unroll
                for (int j = 0; j < 4; j++)
                    acc[i][j] += a[i] * bb[j];
        }
        __syncthreads();
    }

#pragma unroll
    for (int i = 0; i < 4; i++) {
        int row = m0 + ty * 4 + i;
        float bv = HAS_BIAS ? bias[row] : 0.f;
#pragma unroll
        for (int j = 0; j < 4; j++) {
            int col = n0 + tx * 4 + j;
            float v = acc[i][j] + bv;
            if (HAS_RES) v += res[(size_t)row * ldc + col];
            C[(size_t)row * ldc + col] = v;
        }
    }
}

// ---------------------------------------------------------------------------
extern "C" void kernel_launch(void* const* d_in, const int* in_sizes, int n_in,
                              void* d_out, int out_size)
{
    const float* x   = (const float*)d_in[0];
    const float* n1w = (const float*)d_in[1];
    const float* n1b = (const float*)d_in[2];
    const float* kvw = (const float*)d_in[3];
    const float* kvb = (const float*)d_in[4];
    const float* n2w = (const float*)d_in[5];
    const float* n2b = (const float*)d_in[6];
    const float* ow  = (const float*)d_in[7];
    const float* ob  = (const float*)d_in[8];
    float* out = (float*)d_out;

    float *xn, *kv, *q, *ctx, *o1;
    cudaGetSymbolAddress((void**)&xn,  g_xn);
    cudaGetSymbolAddress((void**)&kv,  g_kv);
    cudaGetSymbolAddress((void**)&q,   g_q);
    cudaGetSymbolAddress((void**)&ctx, g_ctx);
    cudaGetSymbolAddress((void**)&o1,  g_o1);

    const size_t sXN  = (size_t)CCH * NSP;      // per-batch stride of [C, n]
    const size_t sKV  = (size_t)2 * CCH * NSP;  // per-batch stride of [2C, n]
    const size_t sCTX = (size_t)CCH * CCH;

    // 1. GroupNorm1 -> xn
    gn_kernel<<<BATCH * NGRP, 256>>>(x, n1w, n1b, xn, 0);

    // 2. kv = W_kv @ xn + b_kv   (M=1024, N=4096, K=512 per batch; W shared)
    gemm64<false, false, true, false><<<dim3(NSP / 64, (2 * CCH) / 64, BATCH), 256>>>(
        kvw, xn, kv, kvb, nullptr,
        2 * CCH, NSP, CCH, CCH, NSP, NSP,
        0, sXN, sKV, 0);

    // 3. q = softmax_channel(k) * C^-0.5   (reads pre-spatial-softmax k)
    softmax_ch<<<dim3(NSP / 256, BATCH), 256>>>(kv, q, 0.044194173824159216f);

    // 4. k = softmax_spatial(k), in place
    softmax_sp<<<BATCH * CCH, 256>>>(kv);

    // 5. context = K @ V^T   (M=512, N=512, K=4096)
    gemm64<false, true, false, false><<<dim3(CCH / 64, CCH / 64, BATCH), 256>>>(
        kv, kv + (size_t)CCH * NSP, ctx, nullptr, nullptr,
        CCH, CCH, NSP, NSP, NSP, CCH,
        sKV, sKV, sCTX, 0);

    // 6. o1 = context^T @ q   (M=512, N=4096, K=512)
    gemm64<true, false, false, false><<<dim3(NSP / 64, CCH / 64, BATCH), 256>>>(
        ctx, q, o1, nullptr, nullptr,
        CCH, NSP, CCH, CCH, NSP, NSP,
        sCTX, sXN, sXN, 0);

    // 7. h = gelu(GroupNorm2(o1))  (reuse q buffer)
    gn_kernel<<<BATCH * NGRP, 256>>>(o1, n2w, n2b, q, 1);

    // 8. out = W_out @ h + b_out + xn
    gemm64<false, false, true, true><<<dim3(NSP / 64, CCH / 64, BATCH), 256>>>(
        ow, q, out, ob, xn,
        CCH, NSP, CCH, CCH, NSP, NSP,
        0, sXN, sXN, sXN);
}

// round 2
// speedup vs baseline: 1.6909x; 1.6909x over previous
#include <cuda_runtime.h>
#include <math.h>
#include <stdint.h>

#define BATCH 16
#define CCH   512
#define NSP   4096
#define NGRP  16

// Scratch (device globals: allocation-free per harness rules)
__device__ float g_xn [(size_t)BATCH * CCH * NSP];        // normed input (also residual)
__device__ float g_kv [(size_t)BATCH * 2 * CCH * NSP];    // kv conv output; k half softmaxed in place
__device__ float g_q  [(size_t)BATCH * CCH * NSP];        // q = channel-softmax(k); later gelu(gn2(out))
__device__ float g_ctx[(size_t)BATCH * CCH * CCH];        // per-batch C x C context
__device__ float g_o1 [(size_t)BATCH * CCH * NSP];        // attention output

// ---------------------------------------------------------------------------
// GroupNorm (optionally fused exact GELU). One block per (batch, group).
// ---------------------------------------------------------------------------
__global__ void gn_kernel(const float* __restrict__ x, const float* __restrict__ w,
                          const float* __restrict__ b, float* __restrict__ y, int gelu)
{
    const int GE = (CCH / NGRP) * NSP;  // 131072
    size_t base = (size_t)blockIdx.x * GE;
    int tid = threadIdx.x;

    float s = 0.f, s2 = 0.f;
    for (int i = tid; i < GE; i += 256) {
        float v = x[base + i];
        s += v; s2 += v * v;
    }
    __shared__ float sh1[256], sh2[256];
    sh1[tid] = s; sh2[tid] = s2;
    __syncthreads();
    for (int o = 128; o > 0; o >>= 1) {
        if (tid < o) { sh1[tid] += sh1[tid + o]; sh2[tid] += sh2[tid + o]; }
        __syncthreads();
    }
    float mean = sh1[0] / (float)GE;
    float var  = sh2[0] / (float)GE - mean * mean;
    float inv  = rsqrtf(var + 1e-5f);

    int cbase = (blockIdx.x & (NGRP - 1)) << 5;
    for (int i = tid; i < GE; i += 256) {
        int c = cbase + (i >> 12);
        float v = (x[base + i] - mean) * inv * w[c] + b[c];
        if (gelu) v = 0.5f * v * (1.0f + erff(v * 0.70710678118654752f));
        y[base + i] = v;
    }
}

// ---------------------------------------------------------------------------
// Channel softmax: q[b,c,n] = softmax_c(k[b,c,n]) * scale.
// ---------------------------------------------------------------------------
__global__ void softmax_ch(const float* __restrict__ kv, float* __restrict__ q, float scale)
{
    int b = blockIdx.y;
    int n = blockIdx.x * blockDim.x + threadIdx.x;
    const float* kp = kv + (size_t)b * 2 * CCH * NSP + n;

    float m = -1e30f, s = 0.f;
    for (int c = 0; c < CCH; c++) {
        float v = kp[(size_t)c * NSP];
        if (v > m) { s = s * expf(m - v) + 1.0f; m = v; }
        else       { s += expf(v - m); }
    }
    float inv = scale / s;
    float* qp = q + (size_t)b * CCH * NSP + n;
    for (int c = 0; c < CCH; c++)
        qp[(size_t)c * NSP] = expf(kp[(size_t)c * NSP] - m) * inv;
}

// ---------------------------------------------------------------------------
// Spatial softmax, in-place on k half of kv.
// ---------------------------------------------------------------------------
__global__ void softmax_sp(float* __restrict__ kv)
{
    int b = blockIdx.x >> 9;
    int c = blockIdx.x & (CCH - 1);
    float* p = kv + (size_t)b * 2 * CCH * NSP + (size_t)c * NSP;
    int tid = threadIdx.x;
    __shared__ float sh[256];

    float m = -1e30f;
    for (int i = tid; i < NSP; i += 256) m = fmaxf(m, p[i]);
    sh[tid] = m; __syncthreads();
    for (int o = 128; o > 0; o >>= 1) {
        if (tid < o) sh[tid] = fmaxf(sh[tid], sh[tid + o]);
        __syncthreads();
    }
    m = sh[0]; __syncthreads();

    float s = 0.f;
    for (int i = tid; i < NSP; i += 256) s += expf(p[i] - m);
    sh[tid] = s; __syncthreads();
    for (int o = 128; o > 0; o >>= 1) {
        if (tid < o) sh[tid] += sh[tid + o];
        __syncthreads();
    }
    float inv = 1.0f / sh[0];
    for (int i = tid; i < NSP; i += 256) p[i] = expf(p[i] - m) * inv;
}

// ---------------------------------------------------------------------------
// Tensor-core tf32 batched GEMM: C = A*B (+bias[m]) (+res).
// TA: A stored K-major (A[k*lda+m]); TB: B stored N-major (B[n*ldb+k]).
// Block tile 128(M) x 64(N) x 16(K), 256 threads = 8 warps (4m x 2n),
// warp tile 32x32 via mma.sync.m16n8k8.tf32 (2 m-tiles x 4 n-tiles).
// Dims must divide 128/64/16 (true for all four GEMMs here).
// ---------------------------------------------------------------------------
__device__ __forceinline__ uint32_t f2tf32(float f) {
    uint32_t u;
    asm("cvt.rna.tf32.f32 %0, %1;" : "=r"(u) : "f"(f));
    return u;
}

template <bool TA, bool TB, bool HAS_BIAS, bool HAS_RES>
__global__ __launch_bounds__(256)
void gemm_tc(const float* __restrict__ A, const float* __restrict__ B,
             float* __restrict__ C, const float* __restrict__ bias,
             const float* __restrict__ res,
             int M, int N, int K, int lda, int ldb, int ldc,
             size_t sA, size_t sB, size_t sC, size_t sR)
{
    A += (size_t)blockIdx.z * sA;
    B += (size_t)blockIdx.z * sB;
    C += (size_t)blockIdx.z * sC;
    if (HAS_RES) res += (size_t)blockIdx.z * sR;

    __shared__ uint32_t As[16][132];   // [k][m], padded
    __shared__ uint32_t Bs[16][68];    // [k][n], padded

    const int tid  = threadIdx.x;
    const int lane = tid & 31;
    const int warp = tid >> 5;
    const int g = lane >> 2;        // 0..7
    const int t = lane & 3;         // 0..3
    const int wm = (warp >> 1) * 32;
    const int wn = (warp & 1) * 32;
    const int m0 = blockIdx.y * 128;
    const int n0 = blockIdx.x * 64;

    float acc[2][4][4];
#pragma unroll
    for (int i = 0; i < 2; i++)
#pragma unroll
        for (int j = 0; j < 4; j++)
#pragma unroll
            for (int r = 0; r < 4; r++) acc[i][j][r] = 0.f;

    float ra[8], rb[4];

    // prologue: load k0 = 0
#pragma unroll
    for (int i = 0; i < 8; i++) {
        int idx = i * 256 + tid;
        if (TA) { int m = idx & 127, k = idx >> 7; ra[i] = A[(size_t)k * lda + m0 + m]; }
        else    { int m = idx >> 4,  k = idx & 15; ra[i] = A[(size_t)(m0 + m) * lda + k]; }
    }
#pragma unroll
    for (int i = 0; i < 4; i++) {
        int idx = i * 256 + tid;
        if (TB) { int k = idx & 15, n = idx >> 4; rb[i] = B[(size_t)(n0 + n) * ldb + k]; }
        else    { int n = idx & 63, k = idx >> 6; rb[i] = B[(size_t)k * ldb + n0 + n]; }
    }

    for (int k0 = 0; k0 < K; k0 += 16) {
        // stage regs -> smem (tf32 convert)
#pragma unroll
        for (int i = 0; i < 8; i++) {
            int idx = i * 256 + tid;
            int m, k;
            if (TA) { m = idx & 127; k = idx >> 7; }
            else    { m = idx >> 4;  k = idx & 15; }
            As[k][m] = f2tf32(ra[i]);
        }
#pragma unroll
        for (int i = 0; i < 4; i++) {
            int idx = i * 256 + tid;
            int n, k;
            if (TB) { k = idx & 15; n = idx >> 4; }
            else    { n = idx & 63; k = idx >> 6; }
            Bs[k][n] = f2tf32(rb[i]);
        }
        __syncthreads();

        // prefetch next tile
        if (k0 + 16 < K) {
            int kn = k0 + 16;
#pragma unroll
            for (int i = 0; i < 8; i++) {
                int idx = i * 256 + tid;
                if (TA) { int m = idx & 127, k = idx >> 7; ra[i] = A[(size_t)(kn + k) * lda + m0 + m]; }
                else    { int m = idx >> 4,  k = idx & 15; ra[i] = A[(size_t)(m0 + m) * lda + kn + k]; }
            }
#pragma unroll
            for (int i = 0; i < 4; i++) {
                int idx = i * 256 + tid;
                if (TB) { int k = idx & 15, n = idx >> 4; rb[i] = B[(size_t)(n0 + n) * ldb + kn + k]; }
                else    { int n = idx & 63, k = idx >> 6; rb[i] = B[(size_t)(kn + k) * ldb + n0 + n]; }
            }
        }

        // compute: two k8 steps
#pragma unroll
        for (int kk = 0; kk < 16; kk += 8) {
            uint32_t af[2][4], bf[4][2];
#pragma unroll
            for (int im = 0; im < 2; im++) {
                int mb = wm + im * 16;
                af[im][0] = As[kk + t    ][mb + g    ];
                af[im][1] = As[kk + t    ][mb + g + 8];
                af[im][2] = As[kk + t + 4][mb + g    ];
                af[im][3] = As[kk + t + 4][mb + g + 8];
            }
#pragma unroll
            for (int in = 0; in < 4; in++) {
                int nb = wn + in * 8;
                bf[in][0] = Bs[kk + t    ][nb + g];
                bf[in][1] = Bs[kk + t + 4][nb + g];
            }
#pragma unroll
            for (int im = 0; im < 2; im++)
#pragma unroll
                for (int in = 0; in < 4; in++) {
                    asm volatile(
                        "mma.sync.aligned.m16n8k8.row.col.f32.tf32.tf32.f32 "
                        "{%0,%1,%2,%3},{%4,%5,%6,%7},{%8,%9},{%0,%1,%2,%3};\n"
                        : "+f"(acc[im][in][0]), "+f"(acc[im][in][1]),
                          "+f"(acc[im][in][2]), "+f"(acc[im][in][3])
                        : "r"(af[im][0]), "r"(af[im][1]), "r"(af[im][2]), "r"(af[im][3]),
                          "r"(bf[in][0]), "r"(bf[in][1]));
                }
        }
        __syncthreads();
    }

    // epilogue
#pragma unroll
    for (int im = 0; im < 2; im++) {
        int r0 = m0 + wm + im * 16 + g;
        int r1 = r0 + 8;
        float bv0 = HAS_BIAS ? bias[r0] : 0.f;
        float bv1 = HAS_BIAS ? bias[r1] : 0.f;
#pragma unroll
        for (int in = 0; in < 4; in++) {
            int c0 = n0 + wn + in * 8 + 2 * t;
            float v0 = acc[im][in][0] + bv0;
            float v1 = acc[im][in][1] + bv0;
            float v2 = acc[im][in][2] + bv1;
            float v3 = acc[im][in][3] + bv1;
            if (HAS_RES) {
                v0 += res[(size_t)r0 * ldc + c0];
                v1 += res[(size_t)r0 * ldc + c0 + 1];
                v2 += res[(size_t)r1 * ldc + c0];
                v3 += res[(size_t)r1 * ldc + c0 + 1];
            }
            C[(size_t)r0 * ldc + c0]     = v0;
            C[(size_t)r0 * ldc + c0 + 1] = v1;
            C[(size_t)r1 * ldc + c0]     = v2;
            C[(size_t)r1 * ldc + c0 + 1] = v3;
        }
    }
}

// ---------------------------------------------------------------------------
extern "C" void kernel_launch(void* const* d_in, const int* in_sizes, int n_in,
                              void* d_out, int out_size)
{
    const float* x   = (const float*)d_in[0];
    const float* n1w = (const float*)d_in[1];
    const float* n1b = (const float*)d_in[2];
    const float* kvw = (const float*)d_in[3];
    const float* kvb = (const float*)d_in[4];
    const float* n2w = (const float*)d_in[5];
    const float* n2b = (const float*)d_in[6];
    const float* ow  = (const float*)d_in[7];
    const float* ob  = (const float*)d_in[8];
    float* out = (float*)d_out;

    float *xn, *kv, *q, *ctx, *o1;
    cudaGetSymbolAddress((void**)&xn,  g_xn);
    cudaGetSymbolAddress((void**)&kv,  g_kv);
    cudaGetSymbolAddress((void**)&q,   g_q);
    cudaGetSymbolAddress((void**)&ctx, g_ctx);
    cudaGetSymbolAddress((void**)&o1,  g_o1);

    const size_t sXN  = (size_t)CCH * NSP;
    const size_t sKV  = (size_t)2 * CCH * NSP;
    const size_t sCTX = (size_t)CCH * CCH;

    // 1. GroupNorm1 -> xn
    gn_kernel<<<BATCH * NGRP, 256>>>(x, n1w, n1b, xn, 0);

    // 2. kv = W_kv @ xn + b_kv   (M=1024, N=4096, K=512)
    gemm_tc<false, false, true, false><<<dim3(NSP / 64, (2 * CCH) / 128, BATCH), 256>>>(
        kvw, xn, kv, kvb, nullptr,
        2 * CCH, NSP, CCH, CCH, NSP, NSP,
        0, sXN, sKV, 0);

    // 3. q = softmax_channel(k) * C^-0.5
    softmax_ch<<<dim3(NSP / 256, BATCH), 256>>>(kv, q, 0.044194173824159216f);

    // 4. k = softmax_spatial(k), in place
    softmax_sp<<<BATCH * CCH, 256>>>(kv);

    // 5. context = K @ V^T   (M=512, N=512, K=4096)
    gemm_tc<false, true, false, false><<<dim3(CCH / 64, CCH / 128, BATCH), 256>>>(
        kv, kv + (size_t)CCH * NSP, ctx, nullptr, nullptr,
        CCH, CCH, NSP, NSP, NSP, CCH,
        sKV, sKV, sCTX, 0);

    // 6. o1 = context^T @ q   (M=512, N=4096, K=512)
    gemm_tc<true, false, false, false><<<dim3(NSP / 64, CCH / 128, BATCH), 256>>>(
        ctx, q, o1, nullptr, nullptr,
        CCH, NSP, CCH, CCH, NSP, NSP,
        sCTX, sXN, sXN, 0);

    // 7. h = gelu(GroupNorm2(o1))  (reuse q buffer)
    gn_kernel<<<BATCH * NGRP, 256>>>(o1, n2w, n2b, q, 1);

    // 8. out = W_out @ h + b_out + xn
    gemm_tc<false, false, true, true><<<dim3(NSP / 64, CCH / 128, BATCH), 256>>>(
        ow, q, out, ob, xn,
        CCH, NSP, CCH, CCH, NSP, NSP,
        0, sXN, sXN, sXN);
}

// round 4
// speedup vs baseline: 2.8574x; 1.6899x over previous
#include <cuda_runtime.h>
#include <math.h>
#include <stdint.h>

#define BATCH 16
#define CCH   512
#define NSP   4096
#define NGRP  16

// Scratch (device globals: allocation-free per harness rules)
__device__ float g_xn [(size_t)BATCH * CCH * NSP];        // normed input (also residual)
__device__ float g_kv [(size_t)BATCH * 2 * CCH * NSP];    // kv conv; k half softmaxed in place
__device__ float g_q  [(size_t)BATCH * CCH * NSP];        // q; later h = gelu(gn2(o1))
__device__ float g_ctx[(size_t)BATCH * CCH * CCH];        // per-batch C x C context [d][e]
__device__ float g_o1 [(size_t)BATCH * CCH * NSP];        // attention output

// ---------------------------------------------------------------------------
__device__ __forceinline__ uint32_t smem_u32(const void* p) {
    uint32_t a;
    asm("{ .reg .u64 t; cvta.to.shared.u64 t, %1; cvt.u32.u64 %0, t; }" : "=r"(a) : "l"(p));
    return a;
}
__device__ __forceinline__ uint32_t f2tf32(float f) {
    uint32_t u;
    asm("cvt.rna.tf32.f32 %0, %1;" : "=r"(u) : "f"(f));
    return u;
}
__device__ __forceinline__ void cp16(uint32_t dst, const float* src) {
    asm volatile("cp.async.cg.shared.global [%0], [%1], 16;" :: "r"(dst), "l"(src) : "memory");
}

// ---------------------------------------------------------------------------
// GroupNorm (+optional exact GELU). One block per (batch, group).
// ---------------------------------------------------------------------------
__global__ void gn_kernel(const float* __restrict__ x, const float* __restrict__ w,
                          const float* __restrict__ b, float* __restrict__ y, int gelu)
{
    const int GE = (CCH / NGRP) * NSP;  // 131072
    size_t base = (size_t)blockIdx.x * GE;
    int tid = threadIdx.x;

    float s = 0.f, s2 = 0.f;
    for (int i = tid; i < GE; i += 256) {
        float v = x[base + i];
        s += v; s2 += v * v;
    }
    __shared__ float sh1[256], sh2[256];
    sh1[tid] = s; sh2[tid] = s2;
    __syncthreads();
    for (int o = 128; o > 0; o >>= 1) {
        if (tid < o) { sh1[tid] += sh1[tid + o]; sh2[tid] += sh2[tid + o]; }
        __syncthreads();
    }
    float mean = sh1[0] / (float)GE;
    float var  = sh2[0] / (float)GE - mean * mean;
    float inv  = rsqrtf(var + 1e-5f);

    int cbase = (blockIdx.x & (NGRP - 1)) << 5;
    for (int i = tid; i < GE; i += 256) {
        int c = cbase + (i >> 12);
        float v = (x[base + i] - mean) * inv * w[c] + b[c];
        if (gelu) v = 0.5f * v * (1.0f + erff(v * 0.70710678118654752f));
        y[base + i] = v;
    }
}

// ---------------------------------------------------------------------------
// Channel softmax: q[b,c,n] = softmax_c(k[b,c,n]) * scale.
// ---------------------------------------------------------------------------
__global__ void softmax_ch(const float* __restrict__ kv, float* __restrict__ q, float scale)
{
    int b = blockIdx.y;
    int n = blockIdx.x * blockDim.x + threadIdx.x;
    const float* kp = kv + (size_t)b * 2 * CCH * NSP + n;

    float m = -1e30f, s = 0.f;
    for (int c = 0; c < CCH; c++) {
        float v = kp[(size_t)c * NSP];
        if (v > m) { s = s * expf(m - v) + 1.0f; m = v; }
        else       { s += expf(v - m); }
    }
    float inv = scale / s;
    float* qp = q + (size_t)b * CCH * NSP + n;
    for (int c = 0; c < CCH; c++)
        qp[(size_t)c * NSP] = expf(kp[(size_t)c * NSP] - m) * inv;
}

// ---------------------------------------------------------------------------
// Spatial softmax, in-place on k half of kv.
// ---------------------------------------------------------------------------
__global__ void softmax_sp(float* __restrict__ kv)
{
    int b = blockIdx.x >> 9;
    int c = blockIdx.x & (CCH - 1);
    float* p = kv + (size_t)b * 2 * CCH * NSP + (size_t)c * NSP;
    int tid = threadIdx.x;
    __shared__ float sh[256];

    float m = -1e30f;
    for (int i = tid; i < NSP; i += 256) m = fmaxf(m, p[i]);
    sh[tid] = m; __syncthreads();
    for (int o = 128; o > 0; o >>= 1) {
        if (tid < o) sh[tid] = fmaxf(sh[tid], sh[tid + o]);
        __syncthreads();
    }
    m = sh[0]; __syncthreads();

    float s = 0.f;
    for (int i = tid; i < NSP; i += 256) s += expf(p[i] - m);
    sh[tid] = s; __syncthreads();
    for (int o = 128; o > 0; o >>= 1) {
        if (tid < o) sh[tid] += sh[tid + o];
        __syncthreads();
    }
    float inv = 1.0f / sh[0];
    for (int i = tid; i < NSP; i += 256) p[i] = expf(p[i] - m) * inv;
}

// ---------------------------------------------------------------------------
// tf32 mma.sync batched GEMM, cp.async double-buffered.
// C[m,n] = sum_k A(m,k)*B(n,k)  (+bias[m]) (+res[m,n])
// TA: A stored K-major (A[k*lda+m]), else row-major (A[m*lda+k]).
// TB: B stored N-major/K-contig (B[n*ldb+k]), else K-major (B[k*ldb+n]).
// Block tile 128x128x16, 128 threads (4 warps, 2m x 2n), warp tile 64x64.
// Smem: row-major operand -> [r][20] (16 data + 4 pad floats);
//       k-major operand   -> [k][136] (128 data + 8 pad floats). Both 16B-OK.
// ---------------------------------------------------------------------------
template <bool TA, bool TB, bool HAS_BIAS, bool HAS_RES>
__global__ __launch_bounds__(128, 2)
void gemm_mma(const float* __restrict__ A, const float* __restrict__ B,
              float* __restrict__ C, const float* __restrict__ bias,
              const float* __restrict__ res,
              int lda, int ldb, int ldc, int K,
              size_t sA, size_t sB, size_t sC)
{
    constexpr int ASZ = TA ? (16 * 136) : (128 * 20);
    constexpr int BSZ = TB ? (128 * 20) : (16 * 136);
    __shared__ float As[2][ASZ];
    __shared__ float Bs[2][BSZ];

    A += (size_t)blockIdx.z * sA;
    B += (size_t)blockIdx.z * sB;
    C += (size_t)blockIdx.z * sC;
    if (HAS_RES) res += (size_t)blockIdx.z * sC;

    const int tid  = threadIdx.x;
    const int lane = tid & 31;
    const int warp = tid >> 5;
    const int g = lane >> 2;          // 0..7
    const int t = lane & 3;           // 0..3
    const int wm = (warp & 1) * 64;
    const int wn = (warp >> 1) * 64;
    const int m0 = blockIdx.y * 128;
    const int n0 = blockIdx.x * 128;

    const uint32_t aBase = smem_u32(As);
    const uint32_t bBase = smem_u32(Bs);

    float acc[4][8][4];
#pragma unroll
    for (int i = 0; i < 4; i++)
#pragma unroll
        for (int j = 0; j < 8; j++)
#pragma unroll
            for (int r = 0; r < 4; r++) acc[i][j][r] = 0.f;

    auto load_tile = [&](int k0, int d) {
        uint32_t ab = aBase + d * (ASZ * 4);
#pragma unroll
        for (int i = 0; i < 4; i++) {
            int id = i * 128 + tid;
            if (TA) { int k = id >> 5, cc = id & 31;
                      cp16(ab + (k * 136 + cc * 4) * 4, A + (size_t)(k0 + k) * lda + m0 + cc * 4); }
            else    { int m = id >> 2, cc = id & 3;
                      cp16(ab + (m * 20 + cc * 4) * 4, A + (size_t)(m0 + m) * lda + k0 + cc * 4); }
        }
        uint32_t bb = bBase + d * (BSZ * 4);
#pragma unroll
        for (int i = 0; i < 4; i++) {
            int id = i * 128 + tid;
            if (TB) { int n = id >> 2, cc = id & 3;
                      cp16(bb + (n * 20 + cc * 4) * 4, B + (size_t)(n0 + n) * ldb + k0 + cc * 4); }
            else    { int k = id >> 5, cc = id & 31;
                      cp16(bb + (k * 136 + cc * 4) * 4, B + (size_t)(k0 + k) * ldb + n0 + cc * 4); }
        }
        asm volatile("cp.async.commit_group;" ::: "memory");
    };

    const int T = K / 16;
    load_tile(0, 0);

    for (int tt = 0; tt < T; tt++) {
        int d = tt & 1;
        if (tt + 1 < T) {
            load_tile((tt + 1) * 16, d ^ 1);
            asm volatile("cp.async.wait_group 1;" ::: "memory");
        } else {
            asm volatile("cp.async.wait_group 0;" ::: "memory");
        }
        __syncthreads();

        const float* __restrict__ a = As[d];
        const float* __restrict__ b = Bs[d];

#pragma unroll
        for (int kk = 0; kk < 16; kk += 8) {
            uint32_t af[4][4], bf[8][2];
#pragma unroll
            for (int im = 0; im < 4; im++) {
                int mb = wm + im * 16;
                if (TA) {
                    af[im][0] = f2tf32(a[(kk + t    ) * 136 + mb + g    ]);
                    af[im][1] = f2tf32(a[(kk + t    ) * 136 + mb + g + 8]);
                    af[im][2] = f2tf32(a[(kk + t + 4) * 136 + mb + g    ]);
                    af[im][3] = f2tf32(a[(kk + t + 4) * 136 + mb + g + 8]);
                } else {
                    af[im][0] = f2tf32(a[(mb + g    ) * 20 + kk + t    ]);
                    af[im][1] = f2tf32(a[(mb + g + 8) * 20 + kk + t    ]);
                    af[im][2] = f2tf32(a[(mb + g    ) * 20 + kk + t + 4]);
                    af[im][3] = f2tf32(a[(mb + g + 8) * 20 + kk + t + 4]);
                }
            }
#pragma unroll
            for (int in = 0; in < 8; in++) {
                int nb = wn + in * 8;
                if (TB) {
                    bf[in][0] = f2tf32(b[(nb + g) * 20 + kk + t    ]);
                    bf[in][1] = f2tf32(b[(nb + g) * 20 + kk + t + 4]);
                } else {
                    bf[in][0] = f2tf32(b[(kk + t    ) * 136 + nb + g]);
                    bf[in][1] = f2tf32(b[(kk + t + 4) * 136 + nb + g]);
                }
            }
#pragma unroll
            for (int im = 0; im < 4; im++)
#pragma unroll
                for (int in = 0; in < 8; in++) {
                    asm volatile(
                        "mma.sync.aligned.m16n8k8.row.col.f32.tf32.tf32.f32 "
                        "{%0,%1,%2,%3},{%4,%5,%6,%7},{%8,%9},{%0,%1,%2,%3};\n"
                        : "+f"(acc[im][in][0]), "+f"(acc[im][in][1]),
                          "+f"(acc[im][in][2]), "+f"(acc[im][in][3])
                        : "r"(af[im][0]), "r"(af[im][1]), "r"(af[im][2]), "r"(af[im][3]),
                          "r"(bf[in][0]), "r"(bf[in][1]));
                }
        }
        __syncthreads();
    }

    // epilogue (float2 stores; mma row pair g / g+8, cols 2t, 2t+1)
#pragma unroll
    for (int im = 0; im < 4; im++) {
        int r0 = m0 + wm + im * 16 + g;
        int r1 = r0 + 8;
        float bv0 = HAS_BIAS ? bias[r0] : 0.f;
        float bv1 = HAS_BIAS ? bias[r1] : 0.f;
#pragma unroll
        for (int in = 0; in < 8; in++) {
            int c0 = n0 + wn + in * 8 + 2 * t;
            float2 v01 = make_float2(acc[im][in][0] + bv0, acc[im][in][1] + bv0);
            float2 v23 = make_float2(acc[im][in][2] + bv1, acc[im][in][3] + bv1);
            if (HAS_RES) {
                float2 e0 = *reinterpret_cast<const float2*>(&res[(size_t)r0 * ldc + c0]);
                float2 e1 = *reinterpret_cast<const float2*>(&res[(size_t)r1 * ldc + c0]);
                v01.x += e0.x; v01.y += e0.y;
                v23.x += e1.x; v23.y += e1.y;
            }
            *reinterpret_cast<float2*>(&C[(size_t)r0 * ldc + c0]) = v01;
            *reinterpret_cast<float2*>(&C[(size_t)r1 * ldc + c0]) = v23;
        }
    }
}

// ---------------------------------------------------------------------------
extern "C" void kernel_launch(void* const* d_in, const int* in_sizes, int n_in,
                              void* d_out, int out_size)
{
    const float* x   = (const float*)d_in[0];
    const float* n1w = (const float*)d_in[1];
    const float* n1b = (const float*)d_in[2];
    const float* kvw = (const float*)d_in[3];
    const float* kvb = (const float*)d_in[4];
    const float* n2w = (const float*)d_in[5];
    const float* n2b = (const float*)d_in[6];
    const float* ow  = (const float*)d_in[7];
    const float* ob  = (const float*)d_in[8];
    float* out = (float*)d_out;

    float *xn, *kv, *q, *ctx, *o1;
    cudaGetSymbolAddress((void**)&xn,  g_xn);
    cudaGetSymbolAddress((void**)&kv,  g_kv);
    cudaGetSymbolAddress((void**)&q,   g_q);
    cudaGetSymbolAddress((void**)&ctx, g_ctx);
    cudaGetSymbolAddress((void**)&o1,  g_o1);

    const size_t sXN  = (size_t)CCH * NSP;
    const size_t sKV  = (size_t)2 * CCH * NSP;
    const size_t sCTX = (size_t)CCH * CCH;

    // 1. GroupNorm1 -> xn
    gn_kernel<<<BATCH * NGRP, 256>>>(x, n1w, n1b, xn, 0);

    // 2. kv = W_kv @ xn + b_kv   (M=1024, N=4096, K=512)
    gemm_mma<false, false, true, false><<<dim3(NSP / 128, (2 * CCH) / 128, BATCH), 128>>>(
        kvw, xn, kv, kvb, nullptr, CCH, NSP, NSP, CCH, 0, sXN, sKV);

    // 3. q = softmax_channel(k) * C^-0.5 ; spatial softmax in-place on k
    softmax_ch<<<dim3(NSP / 256, BATCH), 256>>>(kv, q, 0.044194173824159216f);
    softmax_sp<<<BATCH * CCH, 256>>>(kv);

    // 4. ctx[d,e] = sum_n k[d,n]*v[e,n]   (M=512, N=512, K=4096)
    gemm_mma<false, true, false, false><<<dim3(CCH / 128, CCH / 128, BATCH), 128>>>(
        kv, kv + (size_t)CCH * NSP, ctx, nullptr, nullptr,
        NSP, NSP, CCH, NSP, sKV, sKV, sCTX);

    // 5. o1[e,n] = sum_d ctx[d,e]*q[d,n]  (M=512(e), N=4096, K=512(d); A K-major)
    gemm_mma<true, false, false, false><<<dim3(NSP / 128, CCH / 128, BATCH), 128>>>(
        ctx, q, o1, nullptr, nullptr, CCH, NSP, NSP, CCH, sCTX, sXN, sXN);

    // 6. h = gelu(GN2(o1)) -> q (reuse)
    gn_kernel<<<BATCH * NGRP, 256>>>(o1, n2w, n2b, q, 1);

    // 7. out = W_out @ h + b_out + xn
    gemm_mma<false, false, true, true><<<dim3(NSP / 128, CCH / 128, BATCH), 128>>>(
        ow, q, out, ob, xn, CCH, NSP, NSP, CCH, 0, sXN, sXN);
}

// round 5
// speedup vs baseline: 3.4869x; 1.2203x over previous
#include <cuda_runtime.h>
#include <cuda_fp16.h>
#include <math.h>
#include <stdint.h>

#define BATCH 16
#define CCH   512
#define NSP   4096
#define NGRP  16

// Scratch (device globals: allocation-free per harness rules)
__device__ float  g_xn [(size_t)BATCH * CCH * NSP];       // normed input (fp32 residual)
__device__ float  g_kv [(size_t)BATCH * 2 * CCH * NSP];   // kv conv; k half softmaxed in place
__device__ float  g_q  [(size_t)BATCH * CCH * NSP];       // q fp32; later h = gelu(gn2(o1))
__device__ float  g_o1 [(size_t)BATCH * CCH * NSP];       // attention output fp32
__device__ __half g_xnT16[(size_t)BATCH * CCH * NSP];     // xn^T [n][c] fp16
__device__ __half g_kv16 [(size_t)BATCH * 2 * CCH * NSP]; // k16 [d][n], v16 [e][n]
__device__ __half g_qT16 [(size_t)BATCH * CCH * NSP];     // q^T [n][d] fp16
__device__ __half g_hT16 [(size_t)BATCH * CCH * NSP];     // h^T [n][c] fp16
__device__ __half g_ctx16[(size_t)BATCH * CCH * CCH];     // ctx2 [e][d] fp16
__device__ __half g_w16  [1024 * 512 + 512 * 512];        // kvw16, ow16

// ---------------------------------------------------------------------------
__device__ __forceinline__ uint32_t smem_u32(const void* p) {
    uint32_t a;
    asm("{ .reg .u64 t; cvta.to.shared.u64 t, %1; cvt.u32.u64 %0, t; }" : "=r"(a) : "l"(p));
    return a;
}
__device__ __forceinline__ void cp16(uint32_t dst, const void* src) {
    asm volatile("cp.async.cg.shared.global [%0], [%1], 16;" :: "r"(dst), "l"(src) : "memory");
}

// ---------------------------------------------------------------------------
// GroupNorm (+optional exact GELU). One block per (batch, group).
// ---------------------------------------------------------------------------
__global__ void gn_kernel(const float* __restrict__ x, const float* __restrict__ w,
                          const float* __restrict__ b, float* __restrict__ y, int gelu)
{
    const int GE = (CCH / NGRP) * NSP;  // 131072
    size_t base = (size_t)blockIdx.x * GE;
    int tid = threadIdx.x;

    float s = 0.f, s2 = 0.f;
    for (int i = tid; i < GE; i += 256) {
        float v = x[base + i];
        s += v; s2 += v * v;
    }
    __shared__ float sh1[256], sh2[256];
    sh1[tid] = s; sh2[tid] = s2;
    __syncthreads();
    for (int o = 128; o > 0; o >>= 1) {
        if (tid < o) { sh1[tid] += sh1[tid + o]; sh2[tid] += sh2[tid + o]; }
        __syncthreads();
    }
    float mean = sh1[0] / (float)GE;
    float var  = sh2[0] / (float)GE - mean * mean;
    float inv  = rsqrtf(var + 1e-5f);

    int cbase = (blockIdx.x & (NGRP - 1)) << 5;
    for (int i = tid; i < GE; i += 256) {
        int c = cbase + (i >> 12);
        float v = (x[base + i] - mean) * inv * w[c] + b[c];
        if (gelu) v = 0.5f * v * (1.0f + erff(v * 0.70710678118654752f));
        y[base + i] = v;
    }
}

// ---------------------------------------------------------------------------
// Channel softmax: q[b,c,n] = softmax_c(k[b,c,n]) * scale (fp32 out).
// ---------------------------------------------------------------------------
__global__ void softmax_ch(const float* __restrict__ kv, float* __restrict__ q, float scale)
{
    int b = blockIdx.y;
    int n = blockIdx.x * blockDim.x + threadIdx.x;
    const float* kp = kv + (size_t)b * 2 * CCH * NSP + n;

    float m = -1e30f, s = 0.f;
    for (int c = 0; c < CCH; c++) {
        float v = kp[(size_t)c * NSP];
        if (v > m) { s = s * expf(m - v) + 1.0f; m = v; }
        else       { s += expf(v - m); }
    }
    float inv = scale / s;
    float* qp = q + (size_t)b * CCH * NSP + n;
    for (int c = 0; c < CCH; c++)
        qp[(size_t)c * NSP] = expf(kp[(size_t)c * NSP] - m) * inv;
}

// ---------------------------------------------------------------------------
// Spatial softmax, in-place on k half of kv.
// ---------------------------------------------------------------------------
__global__ void softmax_sp(float* __restrict__ kv)
{
    int b = blockIdx.x >> 9;
    int c = blockIdx.x & (CCH - 1);
    float* p = kv + (size_t)b * 2 * CCH * NSP + (size_t)c * NSP;
    int tid = threadIdx.x;
    __shared__ float sh[256];

    float m = -1e30f;
    for (int i = tid; i < NSP; i += 256) m = fmaxf(m, p[i]);
    sh[tid] = m; __syncthreads();
    for (int o = 128; o > 0; o >>= 1) {
        if (tid < o) sh[tid] = fmaxf(sh[tid], sh[tid + o]);
        __syncthreads();
    }
    m = sh[0]; __syncthreads();

    float s = 0.f;
    for (int i = tid; i < NSP; i += 256) s += expf(p[i] - m);
    sh[tid] = s; __syncthreads();
    for (int o = 128; o > 0; o >>= 1) {
        if (tid < o) sh[tid] += sh[tid + o];
        __syncthreads();
    }
    float inv = 1.0f / sh[0];
    for (int i = tid; i < NSP; i += 256) p[i] = expf(p[i] - m) * inv;
}

// ---------------------------------------------------------------------------
// Tiled transpose + fp32->fp16: in [CCH][NSP] -> out [NSP][CCH] per batch.
// ---------------------------------------------------------------------------
__global__ void t32(const float* __restrict__ in, __half* __restrict__ out)
{
    __shared__ float tile[32][33];
    size_t off = (size_t)blockIdx.z * CCH * NSP;
    int c0 = blockIdx.y * 32, n0 = blockIdx.x * 32;
    int tx = threadIdx.x, ty = threadIdx.y;
#pragma unroll
    for (int i = ty; i < 32; i += 8)
        tile[i][tx] = in[off + (size_t)(c0 + i) * NSP + n0 + tx];
    __syncthreads();
#pragma unroll
    for (int i = ty; i < 32; i += 8)
        out[off + (size_t)(n0 + i) * CCH + c0 + tx] = __float2half(tile[tx][i]);
}

// ---------------------------------------------------------------------------
// Flat fp32 -> fp16 convert (vectorized). n4 = element count / 4.
// ---------------------------------------------------------------------------
__global__ void cvt16(const float* __restrict__ in, __half* __restrict__ out, size_t n4)
{
    size_t stride = (size_t)gridDim.x * blockDim.x;
    const float4* in4 = (const float4*)in;
    __half2* o2 = (__half2*)out;
    for (size_t i = (size_t)blockIdx.x * blockDim.x + threadIdx.x; i < n4; i += stride) {
        float4 v = in4[i];
        o2[2 * i]     = __floats2half2_rn(v.x, v.y);
        o2[2 * i + 1] = __floats2half2_rn(v.z, v.w);
    }
}

// ---------------------------------------------------------------------------
// fp16 mma.sync (m16n8k16) batched GEMM, cp.async double-buffered.
// C[m,n] = sum_k A[m,k]*B[n,k]  (+bias[m]) (+res[m,n])
// A: [M][K] fp16 row-major (lda), B: [N][K] fp16 row-major (ldb).
// Block tile 128x128x32, 128 threads (4 warps, 2m x 2n), warp tile 64x64.
// Smem: [row][40] halfs (32 data + 8 pad = 80B rows, conflict-free & 16B-OK).
// ---------------------------------------------------------------------------
template <bool C_HALF, bool HAS_BIAS, bool HAS_RES>
__global__ __launch_bounds__(128, 2)
void gemm_fp16(const __half* __restrict__ A, const __half* __restrict__ B,
               void* __restrict__ Cv, const float* __restrict__ bias,
               const float* __restrict__ res,
               int lda, int ldb, int ldc, int K,
               size_t sA, size_t sB, size_t sC)
{
    __shared__ __half As[2][128 * 40];
    __shared__ __half Bs[2][128 * 40];

    A += (size_t)blockIdx.z * sA;
    B += (size_t)blockIdx.z * sB;
    if (HAS_RES) res += (size_t)blockIdx.z * sC;

    const int tid  = threadIdx.x;
    const int lane = tid & 31;
    const int warp = tid >> 5;
    const int g = lane >> 2;          // 0..7
    const int t = lane & 3;           // 0..3
    const int wm = (warp & 1) * 64;
    const int wn = (warp >> 1) * 64;
    const int m0 = blockIdx.y * 128;
    const int n0 = blockIdx.x * 128;

    const uint32_t aBase = smem_u32(As);
    const uint32_t bBase = smem_u32(Bs);

    float acc[4][8][4];
#pragma unroll
    for (int i = 0; i < 4; i++)
#pragma unroll
        for (int j = 0; j < 8; j++)
#pragma unroll
            for (int r = 0; r < 4; r++) acc[i][j][r] = 0.f;

    auto load_tile = [&](int k0, int d) {
        uint32_t ab = aBase + d * 10240;
        uint32_t bb = bBase + d * 10240;
#pragma unroll
        for (int i = 0; i < 4; i++) {
            int id = i * 128 + tid;
            int r = id >> 2, c = id & 3;
            cp16(ab + r * 80 + c * 16, A + (size_t)(m0 + r) * lda + k0 + c * 8);
            cp16(bb + r * 80 + c * 16, B + (size_t)(n0 + r) * ldb + k0 + c * 8);
        }
        asm volatile("cp.async.commit_group;" ::: "memory");
    };

    const int T = K / 32;
    load_tile(0, 0);

    for (int tt = 0; tt < T; tt++) {
        int d = tt & 1;
        if (tt + 1 < T) {
            load_tile((tt + 1) * 32, d ^ 1);
            asm volatile("cp.async.wait_group 1;" ::: "memory");
        } else {
            asm volatile("cp.async.wait_group 0;" ::: "memory");
        }
        __syncthreads();

        const __half* __restrict__ a = As[d];
        const __half* __restrict__ b = Bs[d];

#pragma unroll
        for (int kk = 0; kk < 32; kk += 16) {
            uint32_t af[4][4], bf[8][2];
#pragma unroll
            for (int im = 0; im < 4; im++) {
                int mb = wm + im * 16;
                af[im][0] = *(const uint32_t*)&a[(mb + g    ) * 40 + kk + 2 * t    ];
                af[im][1] = *(const uint32_t*)&a[(mb + g + 8) * 40 + kk + 2 * t    ];
                af[im][2] = *(const uint32_t*)&a[(mb + g    ) * 40 + kk + 2 * t + 8];
                af[im][3] = *(const uint32_t*)&a[(mb + g + 8) * 40 + kk + 2 * t + 8];
            }
#pragma unroll
            for (int in = 0; in < 8; in++) {
                int nb = wn + in * 8;
                bf[in][0] = *(const uint32_t*)&b[(nb + g) * 40 + kk + 2 * t    ];
                bf[in][1] = *(const uint32_t*)&b[(nb + g) * 40 + kk + 2 * t + 8];
            }
#pragma unroll
            for (int im = 0; im < 4; im++)
#pragma unroll
                for (int in = 0; in < 8; in++) {
                    asm volatile(
                        "mma.sync.aligned.m16n8k16.row.col.f32.f16.f16.f32 "
                        "{%0,%1,%2,%3},{%4,%5,%6,%7},{%8,%9},{%0,%1,%2,%3};\n"
                        : "+f"(acc[im][in][0]), "+f"(acc[im][in][1]),
                          "+f"(acc[im][in][2]), "+f"(acc[im][in][3])
                        : "r"(af[im][0]), "r"(af[im][1]), "r"(af[im][2]), "r"(af[im][3]),
                          "r"(bf[in][0]), "r"(bf[in][1]));
                }
        }
        __syncthreads();
    }

    // epilogue: rows r0=g, r1=g+8; cols 2t, 2t+1
#pragma unroll
    for (int im = 0; im < 4; im++) {
        int r0 = m0 + wm + im * 16 + g;
        int r1 = r0 + 8;
        float bv0 = HAS_BIAS ? bias[r0] : 0.f;
        float bv1 = HAS_BIAS ? bias[r1] : 0.f;
#pragma unroll
        for (int in = 0; in < 8; in++) {
            int c0 = n0 + wn + in * 8 + 2 * t;
            float v0 = acc[im][in][0] + bv0;
            float v1 = acc[im][in][1] + bv0;
            float v2 = acc[im][in][2] + bv1;
            float v3 = acc[im][in][3] + bv1;
            if (C_HALF) {
                __half* C16 = (__half*)Cv + (size_t)blockIdx.z * sC;
                *reinterpret_cast<__half2*>(&C16[(size_t)r0 * ldc + c0]) = __floats2half2_rn(v0, v1);
                *reinterpret_cast<__half2*>(&C16[(size_t)r1 * ldc + c0]) = __floats2half2_rn(v2, v3);
            } else {
                float* C = (float*)Cv + (size_t)blockIdx.z * sC;
                if (HAS_RES) {
                    float2 e0 = *reinterpret_cast<const float2*>(&res[(size_t)r0 * ldc + c0]);
                    float2 e1 = *reinterpret_cast<const float2*>(&res[(size_t)r1 * ldc + c0]);
                    v0 += e0.x; v1 += e0.y; v2 += e1.x; v3 += e1.y;
                }
                *reinterpret_cast<float2*>(&C[(size_t)r0 * ldc + c0]) = make_float2(v0, v1);
                *reinterpret_cast<float2*>(&C[(size_t)r1 * ldc + c0]) = make_float2(v2, v3);
            }
        }
    }
}

// ---------------------------------------------------------------------------
extern "C" void kernel_launch(void* const* d_in, const int* in_sizes, int n_in,
                              void* d_out, int out_size)
{
    const float* x   = (const float*)d_in[0];
    const float* n1w = (const float*)d_in[1];
    const float* n1b = (const float*)d_in[2];
    const float* kvw = (const float*)d_in[3];
    const float* kvb = (const float*)d_in[4];
    const float* n2w = (const float*)d_in[5];
    const float* n2b = (const float*)d_in[6];
    const float* ow  = (const float*)d_in[7];
    const float* ob  = (const float*)d_in[8];
    float* out = (float*)d_out;

    float *xn, *kv, *q, *o1;
    __half *xnT16, *kv16, *qT16, *hT16, *ctx16, *w16;
    cudaGetSymbolAddress((void**)&xn,    g_xn);
    cudaGetSymbolAddress((void**)&kv,    g_kv);
    cudaGetSymbolAddress((void**)&q,     g_q);
    cudaGetSymbolAddress((void**)&o1,    g_o1);
    cudaGetSymbolAddress((void**)&xnT16, g_xnT16);
    cudaGetSymbolAddress((void**)&kv16,  g_kv16);
    cudaGetSymbolAddress((void**)&qT16,  g_qT16);
    cudaGetSymbolAddress((void**)&hT16,  g_hT16);
    cudaGetSymbolAddress((void**)&ctx16, g_ctx16);
    cudaGetSymbolAddress((void**)&w16,   g_w16);

    __half* kvw16 = w16;
    __half* ow16  = w16 + 1024 * 512;

    const size_t sXN  = (size_t)CCH * NSP;
    const size_t sKV  = (size_t)2 * CCH * NSP;
    const size_t sCTX = (size_t)CCH * CCH;

    dim3 tb32(32, 8);
    dim3 tg32(NSP / 32, CCH / 32, BATCH);

    // 0. weight converts (tiny)
    cvt16<<<256, 256>>>(kvw, kvw16, (1024 * 512) / 4);
    cvt16<<<128, 256>>>(ow,  ow16,  (512 * 512) / 4);

    // 1. GroupNorm1 -> xn (fp32); transpose+cvt -> xnT16
    gn_kernel<<<BATCH * NGRP, 256>>>(x, n1w, n1b, xn, 0);
    t32<<<tg32, tb32>>>(xn, xnT16);

    // 2. kv = W_kv @ xn + b_kv   (M=1024, N=4096, K=512)
    gemm_fp16<false, true, false><<<dim3(NSP / 128, 1024 / 128, BATCH), 128>>>(
        kvw16, xnT16, kv, kvb, nullptr, CCH, CCH, NSP, CCH, 0, sXN, sKV);

    // 3. q = softmax_channel(k)*scale (fp32) -> transpose+cvt -> qT16
    softmax_ch<<<dim3(NSP / 256, BATCH), 256>>>(kv, q, 0.044194173824159216f);
    t32<<<tg32, tb32>>>(q, qT16);

    // 4. k = softmax_spatial(k) in place; convert kv -> kv16 (k16, v16)
    softmax_sp<<<BATCH * CCH, 256>>>(kv);
    cvt16<<<8192, 256>>>(kv, kv16, ((size_t)BATCH * 2 * CCH * NSP) / 4);

    // 5. ctx2[e,d] = sum_n v[e,n]*k[d,n]   (M=512, N=512, K=4096) -> fp16
    gemm_fp16<true, false, false><<<dim3(CCH / 128, CCH / 128, BATCH), 128>>>(
        kv16 + (size_t)CCH * NSP, kv16, ctx16, nullptr, nullptr,
        NSP, NSP, CCH, NSP, sKV, sKV, sCTX);

    // 6. o1[e,n] = sum_d ctx2[e,d]*qT[n,d]  (M=512, N=4096, K=512)
    gemm_fp16<false, false, false><<<dim3(NSP / 128, CCH / 128, BATCH), 128>>>(
        ctx16, qT16, o1, nullptr, nullptr, CCH, CCH, NSP, CCH, sCTX, sXN, sXN);

    // 7. h = gelu(GN2(o1)) -> q (fp32 reuse); transpose+cvt -> hT16
    gn_kernel<<<BATCH * NGRP, 256>>>(o1, n2w, n2b, q, 1);
    t32<<<tg32, tb32>>>(q, hT16);

    // 8. out = W_out @ h + b_out + xn
    gemm_fp16<false, true, true><<<dim3(NSP / 128, CCH / 128, BATCH), 128>>>(
        ow16, hT16, out, ob, xn, CCH, CCH, NSP, CCH, 0, sXN, sXN);
}

// round 6
// speedup vs baseline: 3.7776x; 1.0834x over previous
#include <cuda_runtime.h>
#include <cuda_fp16.h>
#include <math.h>
#include <stdint.h>

#define BATCH 16
#define CCH   512
#define NSP   4096
#define NGRP  16

// Scratch (device globals: allocation-free per harness rules)
__device__ float  g_xn [(size_t)BATCH * CCH * NSP];   // normed input fp32 (residual)
__device__ float  g_k  [(size_t)BATCH * CCH * NSP];   // k fp32 (pre-softmax, from kv GEMM)
__device__ float  g_o1 [(size_t)BATCH * CCH * NSP];   // attention output fp32
__device__ __half g_xnT16[(size_t)BATCH * CCH * NSP]; // xn^T [n][c]
__device__ __half g_v16 [(size_t)BATCH * CCH * NSP];  // v fp16 [e][n] (kv GEMM epilogue)
__device__ __half g_k16 [(size_t)BATCH * CCH * NSP];  // spatial-softmaxed k fp16 [d][n]
__device__ __half g_qT16[(size_t)BATCH * CCH * NSP];  // q^T [n][d]
__device__ __half g_hT16[(size_t)BATCH * CCH * NSP];  // h^T [n][c]
__device__ __half g_ctx16[(size_t)BATCH * CCH * CCH]; // ctx2 [e][d]
__device__ __half g_w16 [1024 * 512 + 512 * 512];     // kvw16, ow16

// ---------------------------------------------------------------------------
__device__ __forceinline__ uint32_t smem_u32(const void* p) {
    uint32_t a;
    asm("{ .reg .u64 t; cvta.to.shared.u64 t, %1; cvt.u32.u64 %0, t; }" : "=r"(a) : "l"(p));
    return a;
}
__device__ __forceinline__ void cp16(uint32_t dst, const void* src) {
    asm volatile("cp.async.cg.shared.global [%0], [%1], 16;" :: "r"(dst), "l"(src) : "memory");
}

// ---------------------------------------------------------------------------
// GroupNorm (+optional exact GELU), fused transposed fp16 output.
// One block per (batch, group) = [32 c][4096 n].
// Writes y32 (same layout, optional) and yT16 ([n][c] fp16).
// ---------------------------------------------------------------------------
__global__ void gnT(const float* __restrict__ x, const float* __restrict__ w,
                    const float* __restrict__ b, float* __restrict__ y32,
                    __half* __restrict__ yT16, int gelu)
{
    const int GE = 32 * NSP;
    const int blk = blockIdx.x;
    const int bb = blk >> 4;
    const int cbase = (blk & 15) << 5;
    const size_t base = (size_t)blk * GE;
    const int tid = threadIdx.x;

    // stats
    float s = 0.f, s2 = 0.f;
    for (int i = tid; i < GE; i += 256) {
        float v = x[base + i];
        s += v; s2 += v * v;
    }
    __shared__ float sh1[256], sh2[256];
    sh1[tid] = s; sh2[tid] = s2;
    __syncthreads();
    for (int o = 128; o > 0; o >>= 1) {
        if (tid < o) { sh1[tid] += sh1[tid + o]; sh2[tid] += sh2[tid + o]; }
        __syncthreads();
    }
    float mean = sh1[0] / (float)GE;
    float var  = sh2[0] / (float)GE - mean * mean;
    float inv  = rsqrtf(var + 1e-5f);

    // normalize + write (tiled 32c x 32n for the transposed fp16 output)
    __shared__ float sm[32][33];
    const int tx = tid & 31, ty = tid >> 5;
    __half* yT = yT16 + (size_t)bb * NSP * CCH;

    for (int n0 = 0; n0 < NSP; n0 += 32) {
#pragma unroll
        for (int i = 0; i < 4; i++) {
            int c = ty + i * 8;
            float v = x[base + (size_t)c * NSP + n0 + tx];
            v = (v - mean) * inv * w[cbase + c] + b[cbase + c];
            if (gelu) v = 0.5f * v * (1.0f + erff(v * 0.70710678118654752f));
            if (y32) y32[base + (size_t)c * NSP + n0 + tx] = v;
            sm[tx][c] = v;
        }
        __syncthreads();
#pragma unroll
        for (int i = 0; i < 4; i++) {
            int j = ty + i * 8;
            yT[(size_t)(n0 + j) * CCH + cbase + tx] = __float2half(sm[j][tx]);
        }
        __syncthreads();
    }
}

// ---------------------------------------------------------------------------
// Channel softmax -> transposed fp16 q: qT[n][d] = softmax_d(k[d,n]) * scale.
// 128 threads, one n each; smem transpose for coalesced [n][d] writes.
// ---------------------------------------------------------------------------
__global__ __launch_bounds__(128)
void softmax_chT(const float* __restrict__ k, __half* __restrict__ qT, float scale)
{
    const int bb = blockIdx.y;
    const int nb = blockIdx.x * 128;
    const int tid = threadIdx.x;
    const float* kp = k + (size_t)bb * CCH * NSP + nb + tid;

    float m = -1e30f, s = 0.f;
    for (int c = 0; c < CCH; c++) {
        float v = kp[(size_t)c * NSP];
        if (v > m) { s = s * __expf(m - v) + 1.0f; m = v; }
        else       { s += __expf(v - m); }
    }
    float invs = scale / s;

    __shared__ __half sm[128][66];
    __half* qb = qT + (size_t)bb * NSP * CCH;
    const int lane = tid & 31, wrp = tid >> 5;

    for (int c0 = 0; c0 < CCH; c0 += 64) {
#pragma unroll 8
        for (int cc = 0; cc < 64; cc++)
            sm[tid][cc] = __float2half(__expf(kp[(size_t)(c0 + cc) * NSP] - m) * invs);
        __syncthreads();
#pragma unroll
        for (int it = 0; it < 32; it++) {
            int nl = it * 4 + wrp;
            *(__half2*)&qb[(size_t)(nb + nl) * CCH + c0 + 2 * lane] =
                *(const __half2*)&sm[nl][2 * lane];
        }
        __syncthreads();
    }
}

// ---------------------------------------------------------------------------
// Spatial softmax: k16[d][n] = softmax_n(k[d][n]) as fp16. One block per row.
// ---------------------------------------------------------------------------
__global__ void softmax_spT(const float* __restrict__ k, __half* __restrict__ k16)
{
    const size_t off = (size_t)(blockIdx.x >> 9) * CCH * NSP +
                       (size_t)(blockIdx.x & 511) * NSP;
    const float* p = k + off;
    __half* o = k16 + off;
    const int tid = threadIdx.x;
    __shared__ float sh[256];

    float m = -1e30f;
    for (int i = tid; i < NSP; i += 256) m = fmaxf(m, p[i]);
    sh[tid] = m; __syncthreads();
    for (int oo = 128; oo > 0; oo >>= 1) {
        if (tid < oo) sh[tid] = fmaxf(sh[tid], sh[tid + oo]);
        __syncthreads();
    }
    m = sh[0]; __syncthreads();

    float s = 0.f;
    for (int i = tid; i < NSP; i += 256) s += __expf(p[i] - m);
    sh[tid] = s; __syncthreads();
    for (int oo = 128; oo > 0; oo >>= 1) {
        if (tid < oo) sh[tid] += sh[tid + oo];
        __syncthreads();
    }
    float inv = 1.0f / sh[0];
    for (int i = tid; i < NSP; i += 256)
        o[i] = __float2half(__expf(p[i] - m) * inv);
}

// ---------------------------------------------------------------------------
// Flat fp32 -> fp16 convert (weights only).
// ---------------------------------------------------------------------------
__global__ void cvt16(const float* __restrict__ in, __half* __restrict__ out, size_t n4)
{
    size_t stride = (size_t)gridDim.x * blockDim.x;
    const float4* in4 = (const float4*)in;
    __half2* o2 = (__half2*)out;
    for (size_t i = (size_t)blockIdx.x * blockDim.x + threadIdx.x; i < n4; i += stride) {
        float4 v = in4[i];
        o2[2 * i]     = __floats2half2_rn(v.x, v.y);
        o2[2 * i + 1] = __floats2half2_rn(v.z, v.w);
    }
}

// ---------------------------------------------------------------------------
// fp16 mma.sync (m16n8k16) batched GEMM, cp.async double-buffered.
// C[m,n] = sum_k A[m,k]*B[n,k]  (+bias[m]) (+res[m,n])
// A: [M][K] fp16 row-major, B: [N][K] fp16 row-major.
// Block tile 128x128x32, 128 threads (4 warps, 2m x 2n), warp tile 64x64.
// KV mode: rows <512 -> fp32 to Cv, rows >=512 -> fp16 to C2 (row-512).
// ---------------------------------------------------------------------------
template <bool KV, bool C_HALF, bool HAS_BIAS, bool HAS_RES>
__global__ __launch_bounds__(128, 2)
void gemm_fp16(const __half* __restrict__ A, const __half* __restrict__ B,
               void* __restrict__ Cv, __half* __restrict__ C2,
               const float* __restrict__ bias, const float* __restrict__ res,
               int lda, int ldb, int ldc, int K,
               size_t sA, size_t sB, size_t sC, size_t sC2)
{
    __shared__ __half As[2][128 * 40];
    __shared__ __half Bs[2][128 * 40];

    A += (size_t)blockIdx.z * sA;
    B += (size_t)blockIdx.z * sB;
    if (HAS_RES) res += (size_t)blockIdx.z * sC;

    const int tid  = threadIdx.x;
    const int lane = tid & 31;
    const int warp = tid >> 5;
    const int g = lane >> 2;
    const int t = lane & 3;
    const int wm = (warp & 1) * 64;
    const int wn = (warp >> 1) * 64;
    const int m0 = blockIdx.y * 128;
    const int n0 = blockIdx.x * 128;

    const uint32_t aBase = smem_u32(As);
    const uint32_t bBase = smem_u32(Bs);

    float acc[4][8][4];
#pragma unroll
    for (int i = 0; i < 4; i++)
#pragma unroll
        for (int j = 0; j < 8; j++)
#pragma unroll
            for (int r = 0; r < 4; r++) acc[i][j][r] = 0.f;

    auto load_tile = [&](int k0, int d) {
        uint32_t ab = aBase + d * 10240;
        uint32_t bb = bBase + d * 10240;
#pragma unroll
        for (int i = 0; i < 4; i++) {
            int id = i * 128 + tid;
            int r = id >> 2, c = id & 3;
            cp16(ab + r * 80 + c * 16, A + (size_t)(m0 + r) * lda + k0 + c * 8);
            cp16(bb + r * 80 + c * 16, B + (size_t)(n0 + r) * ldb + k0 + c * 8);
        }
        asm volatile("cp.async.commit_group;" ::: "memory");
    };

    const int T = K / 32;
    load_tile(0, 0);

    for (int tt = 0; tt < T; tt++) {
        int d = tt & 1;
        if (tt + 1 < T) {
            load_tile((tt + 1) * 32, d ^ 1);
            asm volatile("cp.async.wait_group 1;" ::: "memory");
        } else {
            asm volatile("cp.async.wait_group 0;" ::: "memory");
        }
        __syncthreads();

        const __half* __restrict__ a = As[d];
        const __half* __restrict__ b = Bs[d];

#pragma unroll
        for (int kk = 0; kk < 32; kk += 16) {
            uint32_t af[4][4], bf[8][2];
#pragma unroll
            for (int im = 0; im < 4; im++) {
                int mb = wm + im * 16;
                af[im][0] = *(const uint32_t*)&a[(mb + g    ) * 40 + kk + 2 * t    ];
                af[im][1] = *(const uint32_t*)&a[(mb + g + 8) * 40 + kk + 2 * t    ];
                af[im][2] = *(const uint32_t*)&a[(mb + g    ) * 40 + kk + 2 * t + 8];
                af[im][3] = *(const uint32_t*)&a[(mb + g + 8) * 40 + kk + 2 * t + 8];
            }
#pragma unroll
            for (int in = 0; in < 8; in++) {
                int nb = wn + in * 8;
                bf[in][0] = *(const uint32_t*)&b[(nb + g) * 40 + kk + 2 * t    ];
                bf[in][1] = *(const uint32_t*)&b[(nb + g) * 40 + kk + 2 * t + 8];
            }
#pragma unroll
            for (int im = 0; im < 4; im++)
#pragma unroll
                for (int in = 0; in < 8; in++) {
                    asm volatile(
                        "mma.sync.aligned.m16n8k16.row.col.f32.f16.f16.f32 "
                        "{%0,%1,%2,%3},{%4,%5,%6,%7},{%8,%9},{%0,%1,%2,%3};\n"
                        : "+f"(acc[im][in][0]), "+f"(acc[im][in][1]),
                          "+f"(acc[im][in][2]), "+f"(acc[im][in][3])
                        : "r"(af[im][0]), "r"(af[im][1]), "r"(af[im][2]), "r"(af[im][3]),
                          "r"(bf[in][0]), "r"(bf[in][1]));
                }
        }
        __syncthreads();
    }

    // epilogue
    const bool isv = KV && (m0 >= 512);
#pragma unroll
    for (int im = 0; im < 4; im++) {
        int r0 = m0 + wm + im * 16 + g;
        int r1 = r0 + 8;
        float bv0 = HAS_BIAS ? bias[r0] : 0.f;
        float bv1 = HAS_BIAS ? bias[r1] : 0.f;
#pragma unroll
        for (int in = 0; in < 8; in++) {
            int c0 = n0 + wn + in * 8 + 2 * t;
            float v0 = acc[im][in][0] + bv0;
            float v1 = acc[im][in][1] + bv0;
            float v2 = acc[im][in][2] + bv1;
            float v3 = acc[im][in][3] + bv1;
            if (C_HALF || isv) {
                __half* C16 = (C_HALF ? (__half*)Cv + (size_t)blockIdx.z * sC
                                      : C2 + (size_t)blockIdx.z * sC2);
                int rr0 = isv ? r0 - 512 : r0;
                int rr1 = isv ? r1 - 512 : r1;
                *reinterpret_cast<__half2*>(&C16[(size_t)rr0 * ldc + c0]) = __floats2half2_rn(v0, v1);
                *reinterpret_cast<__half2*>(&C16[(size_t)rr1 * ldc + c0]) = __floats2half2_rn(v2, v3);
            } else {
                float* C = (float*)Cv + (size_t)blockIdx.z * sC;
                if (HAS_RES) {
                    float2 e0 = *reinterpret_cast<const float2*>(&res[(size_t)r0 * ldc + c0]);
                    float2 e1 = *reinterpret_cast<const float2*>(&res[(size_t)r1 * ldc + c0]);
                    v0 += e0.x; v1 += e0.y; v2 += e1.x; v3 += e1.y;
                }
                *reinterpret_cast<float2*>(&C[(size_t)r0 * ldc + c0]) = make_float2(v0, v1);
                *reinterpret_cast<float2*>(&C[(size_t)r1 * ldc + c0]) = make_float2(v2, v3);
            }
        }
    }
}

// ---------------------------------------------------------------------------
extern "C" void kernel_launch(void* const* d_in, const int* in_sizes, int n_in,
                              void* d_out, int out_size)
{
    const float* x   = (const float*)d_in[0];
    const float* n1w = (const float*)d_in[1];
    const float* n1b = (const float*)d_in[2];
    const float* kvw = (const float*)d_in[3];
    const float* kvb = (const float*)d_in[4];
    const float* n2w = (const float*)d_in[5];
    const float* n2b = (const float*)d_in[6];
    const float* ow  = (const float*)d_in[7];
    const float* ob  = (const float*)d_in[8];
    float* out = (float*)d_out;

    float *xn, *kf, *o1;
    __half *xnT16, *v16, *k16, *qT16, *hT16, *ctx16, *w16;
    cudaGetSymbolAddress((void**)&xn,    g_xn);
    cudaGetSymbolAddress((void**)&kf,    g_k);
    cudaGetSymbolAddress((void**)&o1,    g_o1);
    cudaGetSymbolAddress((void**)&xnT16, g_xnT16);
    cudaGetSymbolAddress((void**)&v16,   g_v16);
    cudaGetSymbolAddress((void**)&k16,   g_k16);
    cudaGetSymbolAddress((void**)&qT16,  g_qT16);
    cudaGetSymbolAddress((void**)&hT16,  g_hT16);
    cudaGetSymbolAddress((void**)&ctx16, g_ctx16);
    cudaGetSymbolAddress((void**)&w16,   g_w16);

    __half* kvw16 = w16;
    __half* ow16  = w16 + 1024 * 512;

    const size_t sXN  = (size_t)CCH * NSP;
    const size_t sCTX = (size_t)CCH * CCH;

    // 0. weight converts (tiny)
    cvt16<<<256, 256>>>(kvw, kvw16, (1024 * 512) / 4);
    cvt16<<<128, 256>>>(ow,  ow16,  (512 * 512) / 4);

    // 1. GroupNorm1 -> xn fp32 + xnT16 (fused transpose)
    gnT<<<BATCH * NGRP, 256>>>(x, n1w, n1b, xn, xnT16, 0);

    // 2. kv GEMM: k (fp32) and v16 (fp16) split epilogue. M=1024,N=4096,K=512
    gemm_fp16<true, false, true, false><<<dim3(NSP / 128, 1024 / 128, BATCH), 128>>>(
        kvw16, xnT16, kf, v16, kvb, nullptr,
        CCH, CCH, NSP, CCH, 0, sXN, sXN, sXN);

    // 3. channel softmax -> qT16 ; spatial softmax -> k16
    softmax_chT<<<dim3(NSP / 128, BATCH), 128>>>(kf, qT16, 0.044194173824159216f);
    softmax_spT<<<BATCH * CCH, 256>>>(kf, k16);

    // 4. ctx2[e,d] = sum_n v[e,n]*k[d,n]  (M=512,N=512,K=4096) -> fp16
    gemm_fp16<false, true, false, false><<<dim3(CCH / 128, CCH / 128, BATCH), 128>>>(
        v16, k16, ctx16, nullptr, nullptr, nullptr,
        NSP, NSP, CCH, NSP, sXN, sXN, sCTX, 0);

    // 5. o1[e,n] = sum_d ctx2[e,d]*qT[n,d]  (M=512,N=4096,K=512) -> fp32
    gemm_fp16<false, false, false, false><<<dim3(NSP / 128, CCH / 128, BATCH), 128>>>(
        ctx16, qT16, o1, nullptr, nullptr, nullptr,
        CCH, CCH, NSP, CCH, sCTX, sXN, sXN, 0);

    // 6. h = gelu(GN2(o1)) -> hT16 only (fused transpose, no fp32 out)
    gnT<<<BATCH * NGRP, 256>>>(o1, n2w, n2b, nullptr, hT16, 1);

    // 7. out = W_out @ h + b_out + xn
    gemm_fp16<false, false, true, true><<<dim3(NSP / 128, CCH / 128, BATCH), 128>>>(
        ow16, hT16, out, nullptr, ob, xn,
        CCH, CCH, NSP, CCH, 0, sXN, sXN, 0);
}

// round 7
// speedup vs baseline: 3.9903x; 1.0563x over previous
#include <cuda_runtime.h>
#include <cuda_fp16.h>
#include <math.h>
#include <stdint.h>

#define BATCH 16
#define CCH   512
#define NSP   4096
#define NGRP  16

// Scratch (device globals: allocation-free per harness rules)
__device__ float  g_xn [(size_t)BATCH * CCH * NSP];   // normed input fp32 (residual)
__device__ float  g_k  [(size_t)BATCH * CCH * NSP];   // k fp32 (pre-softmax)
__device__ float  g_o1 [(size_t)BATCH * CCH * NSP];   // attention output fp32
__device__ __half g_xnT16[(size_t)BATCH * CCH * NSP]; // xn^T [n][c]
__device__ __half g_v16 [(size_t)BATCH * CCH * NSP];  // v fp16 [e][n]
__device__ __half g_k16 [(size_t)BATCH * CCH * NSP];  // softmaxed k fp16 [d][n]
__device__ __half g_qT16[(size_t)BATCH * CCH * NSP];  // q^T [n][d]
__device__ __half g_hT16[(size_t)BATCH * CCH * NSP];  // h^T [n][c]
__device__ __half g_ctx16[(size_t)BATCH * CCH * CCH]; // ctx2 [e][d]
__device__ __half g_w16 [1024 * 512 + 512 * 512];     // kvw16, ow16

// ---------------------------------------------------------------------------
__device__ __forceinline__ uint32_t smem_u32(const void* p) {
    uint32_t a;
    asm("{ .reg .u64 t; cvta.to.shared.u64 t, %1; cvt.u32.u64 %0, t; }" : "=r"(a) : "l"(p));
    return a;
}
__device__ __forceinline__ void cp16(uint32_t dst, const void* src) {
    asm volatile("cp.async.cg.shared.global [%0], [%1], 16;" :: "r"(dst), "l"(src) : "memory");
}
__device__ __forceinline__ void ldsm4(uint32_t& r0, uint32_t& r1, uint32_t& r2, uint32_t& r3,
                                      uint32_t addr) {
    asm volatile("ldmatrix.sync.aligned.m8n8.x4.shared.b16 {%0,%1,%2,%3}, [%4];"
                 : "=r"(r0), "=r"(r1), "=r"(r2), "=r"(r3) : "r"(addr));
}

// ---------------------------------------------------------------------------
// GroupNorm (+optional exact GELU), fused transposed fp16 output.
// ---------------------------------------------------------------------------
__global__ void gnT(const float* __restrict__ x, const float* __restrict__ w,
                    const float* __restrict__ b, float* __restrict__ y32,
                    __half* __restrict__ yT16, int gelu)
{
    const int GE = 32 * NSP;
    const int blk = blockIdx.x;
    const int bb = blk >> 4;
    const int cbase = (blk & 15) << 5;
    const size_t base = (size_t)blk * GE;
    const int tid = threadIdx.x;

    float s = 0.f, s2 = 0.f;
    for (int i = tid; i < GE; i += 256) {
        float v = x[base + i];
        s += v; s2 += v * v;
    }
    __shared__ float sh1[256], sh2[256];
    sh1[tid] = s; sh2[tid] = s2;
    __syncthreads();
    for (int o = 128; o > 0; o >>= 1) {
        if (tid < o) { sh1[tid] += sh1[tid + o]; sh2[tid] += sh2[tid + o]; }
        __syncthreads();
    }
    float mean = sh1[0] / (float)GE;
    float var  = sh2[0] / (float)GE - mean * mean;
    float inv  = rsqrtf(var + 1e-5f);

    __shared__ float sm[32][33];
    const int tx = tid & 31, ty = tid >> 5;
    __half* yT = yT16 + (size_t)bb * NSP * CCH;

    for (int n0 = 0; n0 < NSP; n0 += 32) {
#pragma unroll
        for (int i = 0; i < 4; i++) {
            int c = ty + i * 8;
            float v = x[base + (size_t)c * NSP + n0 + tx];
            v = (v - mean) * inv * w[cbase + c] + b[cbase + c];
            if (gelu) v = 0.5f * v * (1.0f + erff(v * 0.70710678118654752f));
            if (y32) y32[base + (size_t)c * NSP + n0 + tx] = v;
            sm[tx][c] = v;
        }
        __syncthreads();
#pragma unroll
        for (int i = 0; i < 4; i++) {
            int j = ty + i * 8;
            yT[(size_t)(n0 + j) * CCH + cbase + tx] = __float2half(sm[j][tx]);
        }
        __syncthreads();
    }
}

// ---------------------------------------------------------------------------
// Channel softmax -> transposed fp16 q.
// ---------------------------------------------------------------------------
__global__ __launch_bounds__(128)
void softmax_chT(const float* __restrict__ k, __half* __restrict__ qT, float scale)
{
    const int bb = blockIdx.y;
    const int nb = blockIdx.x * 128;
    const int tid = threadIdx.x;
    const float* kp = k + (size_t)bb * CCH * NSP + nb + tid;

    float m = -1e30f, s = 0.f;
    for (int c = 0; c < CCH; c++) {
        float v = kp[(size_t)c * NSP];
        if (v > m) { s = s * __expf(m - v) + 1.0f; m = v; }
        else       { s += __expf(v - m); }
    }
    float invs = scale / s;

    __shared__ __half sm[128][66];
    __half* qb = qT + (size_t)bb * NSP * CCH;
    const int lane = tid & 31, wrp = tid >> 5;

    for (int c0 = 0; c0 < CCH; c0 += 64) {
#pragma unroll 8
        for (int cc = 0; cc < 64; cc++)
            sm[tid][cc] = __float2half(__expf(kp[(size_t)(c0 + cc) * NSP] - m) * invs);
        __syncthreads();
#pragma unroll
        for (int it = 0; it < 32; it++) {
            int nl = it * 4 + wrp;
            *(__half2*)&qb[(size_t)(nb + nl) * CCH + c0 + 2 * lane] =
                *(const __half2*)&sm[nl][2 * lane];
        }
        __syncthreads();
    }
}

// ---------------------------------------------------------------------------
// Spatial softmax -> fp16.
// ---------------------------------------------------------------------------
__global__ void softmax_spT(const float* __restrict__ k, __half* __restrict__ k16)
{
    const size_t off = (size_t)(blockIdx.x >> 9) * CCH * NSP +
                       (size_t)(blockIdx.x & 511) * NSP;
    const float* p = k + off;
    __half* o = k16 + off;
    const int tid = threadIdx.x;
    __shared__ float sh[256];

    float m = -1e30f;
    for (int i = tid; i < NSP; i += 256) m = fmaxf(m, p[i]);
    sh[tid] = m; __syncthreads();
    for (int oo = 128; oo > 0; oo >>= 1) {
        if (tid < oo) sh[tid] = fmaxf(sh[tid], sh[tid + oo]);
        __syncthreads();
    }
    m = sh[0]; __syncthreads();

    float s = 0.f;
    for (int i = tid; i < NSP; i += 256) s += __expf(p[i] - m);
    sh[tid] = s; __syncthreads();
    for (int oo = 128; oo > 0; oo >>= 1) {
        if (tid < oo) sh[tid] += sh[tid + oo];
        __syncthreads();
    }
    float inv = 1.0f / sh[0];
    for (int i = tid; i < NSP; i += 256)
        o[i] = __float2half(__expf(p[i] - m) * inv);
}

// ---------------------------------------------------------------------------
// Flat fp32 -> fp16 convert (weights only).
// ---------------------------------------------------------------------------
__global__ void cvt16(const float* __restrict__ in, __half* __restrict__ out, size_t n4)
{
    size_t stride = (size_t)gridDim.x * blockDim.x;
    const float4* in4 = (const float4*)in;
    __half2* o2 = (__half2*)out;
    for (size_t i = (size_t)blockIdx.x * blockDim.x + threadIdx.x; i < n4; i += stride) {
        float4 v = in4[i];
        o2[2 * i]     = __floats2half2_rn(v.x, v.y);
        o2[2 * i + 1] = __floats2half2_rn(v.z, v.w);
    }
}

// ---------------------------------------------------------------------------
// fp16 mma.sync (m16n8k16) GEMM, 3-stage cp.async, ldmatrix fragments.
// C[m,n] = sum_k A[m,k]*B[n,k]  (+bias[m]) (+res[m,n])
// A,B: fp16 row-major [M][K], [N][K].
// Block 128x128x32, 256 threads = 8 warps (2m x 4n), warp tile 64x32.
// Smem rows: 32 halfs + 8 pad = 80B (ldmatrix conflict-free at 20-word stride).
// ---------------------------------------------------------------------------
#define STG 10240  // stage bytes per operand (128 rows * 80B)

template <bool KV, bool C_HALF, bool HAS_BIAS, bool HAS_RES>
__global__ __launch_bounds__(256, 2)
void gemm_fp16(const __half* __restrict__ A, const __half* __restrict__ B,
               void* __restrict__ Cv, __half* __restrict__ C2,
               const float* __restrict__ bias, const float* __restrict__ res,
               int lda, int ldb, int ldc, int K,
               size_t sA, size_t sB, size_t sC, size_t sC2)
{
    __shared__ __half As[3][128 * 40];
    __shared__ __half Bs[3][128 * 40];

    A += (size_t)blockIdx.z * sA;
    B += (size_t)blockIdx.z * sB;
    if (HAS_RES) res += (size_t)blockIdx.z * sC;

    const int tid  = threadIdx.x;
    const int lane = tid & 31;
    const int warp = tid >> 5;
    const int g = lane >> 2;
    const int t = lane & 3;
    const int wm = (warp & 1) * 64;
    const int wn = (warp >> 1) * 32;
    const int m0 = blockIdx.y * 128;
    const int n0 = blockIdx.x * 128;

    const uint32_t aBase = smem_u32(As);
    const uint32_t bBase = smem_u32(Bs);

    // ldmatrix per-thread offsets
    const uint32_t aOff = (uint32_t)(wm + (lane & 15)) * 80 + (lane >> 4) * 16;
    const uint32_t bOff = (uint32_t)(wn + (lane & 7) + ((lane >> 4) << 3)) * 80 +
                          ((lane >> 3) & 1) * 16;

    float acc[4][4][4];
#pragma unroll
    for (int i = 0; i < 4; i++)
#pragma unroll
        for (int j = 0; j < 4; j++)
#pragma unroll
            for (int r = 0; r < 4; r++) acc[i][j][r] = 0.f;

    auto load_tile = [&](int k0, int st) {
        uint32_t ab = aBase + st * STG;
        uint32_t bb = bBase + st * STG;
#pragma unroll
        for (int i = 0; i < 2; i++) {
            int id = i * 256 + tid;
            int r = id >> 2, c = id & 3;
            cp16(ab + r * 80 + c * 16, A + (size_t)(m0 + r) * lda + k0 + c * 8);
            cp16(bb + r * 80 + c * 16, B + (size_t)(n0 + r) * ldb + k0 + c * 8);
        }
        asm volatile("cp.async.commit_group;" ::: "memory");
    };

    const int T = K / 32;
    load_tile(0, 0);
    if (T > 1) load_tile(32, 1);

    for (int tt = 0; tt < T; tt++) {
        if (tt + 2 < T) asm volatile("cp.async.wait_group 1;" ::: "memory");
        else            asm volatile("cp.async.wait_group 0;" ::: "memory");
        __syncthreads();

        const int st = tt % 3;
        const uint32_t sa = aBase + st * STG;
        const uint32_t sb = bBase + st * STG;

#pragma unroll
        for (int kk = 0; kk < 2; kk++) {        // two k16 steps; byte offset kk*32
            uint32_t af[4][4], bf[4][2];
#pragma unroll
            for (int im = 0; im < 4; im++)
                ldsm4(af[im][0], af[im][1], af[im][2], af[im][3],
                      sa + aOff + im * 1280 + kk * 32);
#pragma unroll
            for (int p = 0; p < 2; p++)
                ldsm4(bf[2 * p][0], bf[2 * p][1], bf[2 * p + 1][0], bf[2 * p + 1][1],
                      sb + bOff + p * 1280 + kk * 32);
#pragma unroll
            for (int im = 0; im < 4; im++)
#pragma unroll
                for (int in = 0; in < 4; in++) {
                    asm volatile(
                        "mma.sync.aligned.m16n8k16.row.col.f32.f16.f16.f32 "
                        "{%0,%1,%2,%3},{%4,%5,%6,%7},{%8,%9},{%0,%1,%2,%3};\n"
                        : "+f"(acc[im][in][0]), "+f"(acc[im][in][1]),
                          "+f"(acc[im][in][2]), "+f"(acc[im][in][3])
                        : "r"(af[im][0]), "r"(af[im][1]), "r"(af[im][2]), "r"(af[im][3]),
                          "r"(bf[in][0]), "r"(bf[in][1]));
                }
        }

        if (tt + 2 < T) load_tile((tt + 2) * 32, (tt + 2) % 3);
    }

    // epilogue
    const bool isv = KV && (m0 >= 512);
#pragma unroll
    for (int im = 0; im < 4; im++) {
        int r0 = m0 + wm + im * 16 + g;
        int r1 = r0 + 8;
        float bv0 = HAS_BIAS ? bias[r0] : 0.f;
        float bv1 = HAS_BIAS ? bias[r1] : 0.f;
#pragma unroll
        for (int in = 0; in < 4; in++) {
            int c0 = n0 + wn + in * 8 + 2 * t;
            float v0 = acc[im][in][0] + bv0;
            float v1 = acc[im][in][1] + bv0;
            float v2 = acc[im][in][2] + bv1;
            float v3 = acc[im][in][3] + bv1;
            if (C_HALF || isv) {
                __half* C16 = (C_HALF ? (__half*)Cv + (size_t)blockIdx.z * sC
                                      : C2 + (size_t)blockIdx.z * sC2);
                int rr0 = isv ? r0 - 512 : r0;
                int rr1 = isv ? r1 - 512 : r1;
                *reinterpret_cast<__half2*>(&C16[(size_t)rr0 * ldc + c0]) = __floats2half2_rn(v0, v1);
                *reinterpret_cast<__half2*>(&C16[(size_t)rr1 * ldc + c0]) = __floats2half2_rn(v2, v3);
            } else {
                float* C = (float*)Cv + (size_t)blockIdx.z * sC;
                if (HAS_RES) {
                    float2 e0 = *reinterpret_cast<const float2*>(&res[(size_t)r0 * ldc + c0]);
                    float2 e1 = *reinterpret_cast<const float2*>(&res[(size_t)r1 * ldc + c0]);
                    v0 += e0.x; v1 += e0.y; v2 += e1.x; v3 += e1.y;
                }
                *reinterpret_cast<float2*>(&C[(size_t)r0 * ldc + c0]) = make_float2(v0, v1);
                *reinterpret_cast<float2*>(&C[(size_t)r1 * ldc + c0]) = make_float2(v2, v3);
            }
        }
    }
}

// ---------------------------------------------------------------------------
extern "C" void kernel_launch(void* const* d_in, const int* in_sizes, int n_in,
                              void* d_out, int out_size)
{
    const float* x   = (const float*)d_in[0];
    const float* n1w = (const float*)d_in[1];
    const float* n1b = (const float*)d_in[2];
    const float* kvw = (const float*)d_in[3];
    const float* kvb = (const float*)d_in[4];
    const float* n2w = (const float*)d_in[5];
    const float* n2b = (const float*)d_in[6];
    const float* ow  = (const float*)d_in[7];
    const float* ob  = (const float*)d_in[8];
    float* out = (float*)d_out;

    float *xn, *kf, *o1;
    __half *xnT16, *v16, *k16, *qT16, *hT16, *ctx16, *w16;
    cudaGetSymbolAddress((void**)&xn,    g_xn);
    cudaGetSymbolAddress((void**)&kf,    g_k);
    cudaGetSymbolAddress((void**)&o1,    g_o1);
    cudaGetSymbolAddress((void**)&xnT16, g_xnT16);
    cudaGetSymbolAddress((void**)&v16,   g_v16);
    cudaGetSymbolAddress((void**)&k16,   g_k16);
    cudaGetSymbolAddress((void**)&qT16,  g_qT16);
    cudaGetSymbolAddress((void**)&hT16,  g_hT16);
    cudaGetSymbolAddress((void**)&ctx16, g_ctx16);
    cudaGetSymbolAddress((void**)&w16,   g_w16);

    __half* kvw16 = w16;
    __half* ow16  = w16 + 1024 * 512;

    const size_t sXN  = (size_t)CCH * NSP;
    const size_t sCTX = (size_t)CCH * CCH;

    // 0. weight converts (tiny)
    cvt16<<<256, 256>>>(kvw, kvw16, (1024 * 512) / 4);
    cvt16<<<128, 256>>>(ow,  ow16,  (512 * 512) / 4);

    // 1. GroupNorm1 -> xn fp32 + xnT16 (fused transpose)
    gnT<<<BATCH * NGRP, 256>>>(x, n1w, n1b, xn, xnT16, 0);

    // 2. kv GEMM: k (fp32) and v16 (fp16) split epilogue. M=1024,N=4096,K=512
    gemm_fp16<true, false, true, false><<<dim3(NSP / 128, 1024 / 128, BATCH), 256>>>(
        kvw16, xnT16, kf, v16, kvb, nullptr,
        CCH, CCH, NSP, CCH, 0, sXN, sXN, sXN);

    // 3. channel softmax -> qT16 ; spatial softmax -> k16
    softmax_chT<<<dim3(NSP / 128, BATCH), 128>>>(kf, qT16, 0.044194173824159216f);
    softmax_spT<<<BATCH * CCH, 256>>>(kf, k16);

    // 4. ctx2[e,d] = sum_n v[e,n]*k[d,n]  (M=512,N=512,K=4096) -> fp16
    gemm_fp16<false, true, false, false><<<dim3(CCH / 128, CCH / 128, BATCH), 256>>>(
        v16, k16, ctx16, nullptr, nullptr, nullptr,
        NSP, NSP, CCH, NSP, sXN, sXN, sCTX, 0);

    // 5. o1[e,n] = sum_d ctx2[e,d]*qT[n,d]  (M=512,N=4096,K=512) -> fp32
    gemm_fp16<false, false, false, false><<<dim3(NSP / 128, CCH / 128, BATCH), 256>>>(
        ctx16, qT16, o1, nullptr, nullptr, nullptr,
        CCH, CCH, NSP, CCH, sCTX, sXN, sXN, 0);

    // 6. h = gelu(GN2(o1)) -> hT16 only (fused transpose)
    gnT<<<BATCH * NGRP, 256>>>(o1, n2w, n2b, nullptr, hT16, 1);

    // 7. out = W_out @ h + b_out + xn
    gemm_fp16<false, false, true, true><<<dim3(NSP / 128, CCH / 128, BATCH), 256>>>(
        ow16, hT16, out, nullptr, ob, xn,
        CCH, CCH, NSP, CCH, 0, sXN, sXN, 0);
}

// round 8
// speedup vs baseline: 4.7296x; 1.1853x over previous
#include <cuda_runtime.h>
#include <cuda_fp16.h>
#include <math.h>
#include <stdint.h>

#define BATCH 16
#define CCH   512
#define NSP   4096
#define NGRP  16

// Scratch (device globals: allocation-free per harness rules)
__device__ float  g_k  [(size_t)BATCH * CCH * NSP];   // k fp32 (pre-softmax)
__device__ __half g_o116[(size_t)BATCH * CCH * NSP];  // attention output fp16
__device__ __half g_xnT16[(size_t)BATCH * CCH * NSP]; // xn^T [n][c]
__device__ __half g_v16 [(size_t)BATCH * CCH * NSP];  // v fp16 [e][n]
__device__ __half g_k16 [(size_t)BATCH * CCH * NSP];  // softmaxed k fp16 [d][n]
__device__ __half g_qT16[(size_t)BATCH * CCH * NSP];  // q^T [n][d]
__device__ __half g_hT16[(size_t)BATCH * CCH * NSP];  // h^T [n][c]
__device__ __half g_ctx16[(size_t)BATCH * CCH * CCH]; // ctx2 [e][d]
__device__ float2 g_stats[BATCH * NGRP];              // gn1 (mean, inv) per (b, group)
__device__ __half g_w16 [1024 * 512 + 512 * 512];     // kvw16, ow16

// ---------------------------------------------------------------------------
__device__ __forceinline__ uint32_t smem_u32(const void* p) {
    uint32_t a;
    asm("{ .reg .u64 t; cvta.to.shared.u64 t, %1; cvt.u32.u64 %0, t; }" : "=r"(a) : "l"(p));
    return a;
}
__device__ __forceinline__ void cp16(uint32_t dst, const void* src) {
    asm volatile("cp.async.cg.shared.global [%0], [%1], 16;" :: "r"(dst), "l"(src) : "memory");
}
__device__ __forceinline__ void ldsm4(uint32_t& r0, uint32_t& r1, uint32_t& r2, uint32_t& r3,
                                      uint32_t addr) {
    asm volatile("ldmatrix.sync.aligned.m8n8.x4.shared.b16 {%0,%1,%2,%3}, [%4];"
                 : "=r"(r0), "=r"(r1), "=r"(r2), "=r"(r3) : "r"(addr));
}
__device__ __forceinline__ float ldf(const float* p)  { return *p; }
__device__ __forceinline__ float ldf(const __half* p) { return __half2float(*p); }

// ---------------------------------------------------------------------------
// GroupNorm (+optional exact GELU) -> transposed fp16 output only.
// Optionally records (mean, inv) per (batch, group) for later residual recompute.
// One block per (batch, group) = [32 c][4096 n].
// ---------------------------------------------------------------------------
template <typename Tin>
__global__ void gnT(const Tin* __restrict__ x, const float* __restrict__ w,
                    const float* __restrict__ b, __half* __restrict__ yT16,
                    float2* __restrict__ stats, int gelu)
{
    const int GE = 32 * NSP;
    const int blk = blockIdx.x;
    const int bb = blk >> 4;
    const int cbase = (blk & 15) << 5;
    const size_t base = (size_t)blk * GE;
    const int tid = threadIdx.x;

    float s = 0.f, s2 = 0.f;
    for (int i = tid; i < GE; i += 256) {
        float v = ldf(&x[base + i]);
        s += v; s2 += v * v;
    }
    __shared__ float sh1[256], sh2[256];
    sh1[tid] = s; sh2[tid] = s2;
    __syncthreads();
    for (int o = 128; o > 0; o >>= 1) {
        if (tid < o) { sh1[tid] += sh1[tid + o]; sh2[tid] += sh2[tid + o]; }
        __syncthreads();
    }
    float mean = sh1[0] / (float)GE;
    float var  = sh2[0] / (float)GE - mean * mean;
    float inv  = rsqrtf(var + 1e-5f);
    if (stats && tid == 0) stats[blk] = make_float2(mean, inv);

    __shared__ float sm[32][33];
    const int tx = tid & 31, ty = tid >> 5;
    __half* yT = yT16 + (size_t)bb * NSP * CCH;

    for (int n0 = 0; n0 < NSP; n0 += 32) {
#pragma unroll
        for (int i = 0; i < 4; i++) {
            int c = ty + i * 8;
            float v = ldf(&x[base + (size_t)c * NSP + n0 + tx]);
            v = (v - mean) * inv * w[cbase + c] + b[cbase + c];
            if (gelu) v = 0.5f * v * (1.0f + erff(v * 0.70710678118654752f));
            sm[tx][c] = v;
        }
        __syncthreads();
#pragma unroll
        for (int i = 0; i < 4; i++) {
            int j = ty + i * 8;
            yT[(size_t)(n0 + j) * CCH + cbase + tx] = __float2half(sm[j][tx]);
        }
        __syncthreads();
    }
}

// ---------------------------------------------------------------------------
// Channel softmax -> transposed fp16 q.
// ---------------------------------------------------------------------------
__global__ __launch_bounds__(128)
void softmax_chT(const float* __restrict__ k, __half* __restrict__ qT, float scale)
{
    const int bb = blockIdx.y;
    const int nb = blockIdx.x * 128;
    const int tid = threadIdx.x;
    const float* kp = k + (size_t)bb * CCH * NSP + nb + tid;

    float m = -1e30f, s = 0.f;
    for (int c = 0; c < CCH; c++) {
        float v = kp[(size_t)c * NSP];
        if (v > m) { s = s * __expf(m - v) + 1.0f; m = v; }
        else       { s += __expf(v - m); }
    }
    float invs = scale / s;

    __shared__ __half sm[128][66];
    __half* qb = qT + (size_t)bb * NSP * CCH;
    const int lane = tid & 31, wrp = tid >> 5;

    for (int c0 = 0; c0 < CCH; c0 += 64) {
#pragma unroll 8
        for (int cc = 0; cc < 64; cc++)
            sm[tid][cc] = __float2half(__expf(kp[(size_t)(c0 + cc) * NSP] - m) * invs);
        __syncthreads();
#pragma unroll
        for (int it = 0; it < 32; it++) {
            int nl = it * 4 + wrp;
            *(__half2*)&qb[(size_t)(nb + nl) * CCH + c0 + 2 * lane] =
                *(const __half2*)&sm[nl][2 * lane];
        }
        __syncthreads();
    }
}

// ---------------------------------------------------------------------------
// Spatial softmax -> fp16, online (max,sum) in one read pass.
// ---------------------------------------------------------------------------
__global__ void softmax_spT(const float* __restrict__ k, __half* __restrict__ k16)
{
    const size_t off = (size_t)(blockIdx.x >> 9) * CCH * NSP +
                       (size_t)(blockIdx.x & 511) * NSP;
    const float* p = k + off;
    __half* o = k16 + off;
    const int tid = threadIdx.x;
    __shared__ float shm[256], shs[256];

    float m = -1e30f, s = 0.f;
    for (int i = tid; i < NSP; i += 256) {
        float v = p[i];
        if (v > m) { s = s * __expf(m - v) + 1.0f; m = v; }
        else       { s += __expf(v - m); }
    }
    shm[tid] = m; shs[tid] = s;
    __syncthreads();
    for (int oo = 128; oo > 0; oo >>= 1) {
        if (tid < oo) {
            float m2 = shm[tid + oo], s2 = shs[tid + oo];
            float M = fmaxf(shm[tid], m2);
            shs[tid] = shs[tid] * __expf(shm[tid] - M) + s2 * __expf(m2 - M);
            shm[tid] = M;
        }
        __syncthreads();
    }
    m = shm[0];
    float inv = 1.0f / shs[0];
    for (int i = tid; i < NSP; i += 256)
        o[i] = __float2half(__expf(p[i] - m) * inv);
}

// ---------------------------------------------------------------------------
// Flat fp32 -> fp16 convert (weights only).
// ---------------------------------------------------------------------------
__global__ void cvt16(const float* __restrict__ in, __half* __restrict__ out, size_t n4)
{
    size_t stride = (size_t)gridDim.x * blockDim.x;
    const float4* in4 = (const float4*)in;
    __half2* o2 = (__half2*)out;
    for (size_t i = (size_t)blockIdx.x * blockDim.x + threadIdx.x; i < n4; i += stride) {
        float4 v = in4[i];
        o2[2 * i]     = __floats2half2_rn(v.x, v.y);
        o2[2 * i + 1] = __floats2half2_rn(v.z, v.w);
    }
}

// ---------------------------------------------------------------------------
// fp16 mma.sync (m16n8k16) GEMM, 3-stage cp.async, ldmatrix fragments.
// C[m,n] = sum_k A[m,k]*B[n,k]  (+bias[m]) (+residual)
// RESX: residual recomputed from raw x via gn1 stats: (x-mean)*inv*w1+b1.
// Block 128x128x32, 256 threads = 8 warps (2m x 4n), warp tile 64x32.
// ---------------------------------------------------------------------------
#define STG 10240

template <bool KV, bool C_HALF, bool HAS_BIAS, bool RESX>
__global__ __launch_bounds__(256, 2)
void gemm_fp16(const __half* __restrict__ A, const __half* __restrict__ B,
               void* __restrict__ Cv, __half* __restrict__ C2,
               const float* __restrict__ bias,
               const float* __restrict__ resx, const float2* __restrict__ stats,
               const float* __restrict__ resw, const float* __restrict__ resb,
               int lda, int ldb, int ldc, int K,
               size_t sA, size_t sB, size_t sC, size_t sC2)
{
    __shared__ __half As[3][128 * 40];
    __shared__ __half Bs[3][128 * 40];

    A += (size_t)blockIdx.z * sA;
    B += (size_t)blockIdx.z * sB;
    if (RESX) resx += (size_t)blockIdx.z * sC;

    const int tid  = threadIdx.x;
    const int lane = tid & 31;
    const int warp = tid >> 5;
    const int g = lane >> 2;
    const int t = lane & 3;
    const int wm = (warp & 1) * 64;
    const int wn = (warp >> 1) * 32;
    const int m0 = blockIdx.y * 128;
    const int n0 = blockIdx.x * 128;

    const uint32_t aBase = smem_u32(As);
    const uint32_t bBase = smem_u32(Bs);

    const uint32_t aOff = (uint32_t)(wm + (lane & 15)) * 80 + (lane >> 4) * 16;
    const uint32_t bOff = (uint32_t)(wn + (lane & 7) + ((lane >> 4) << 3)) * 80 +
                          ((lane >> 3) & 1) * 16;

    float acc[4][4][4];
#pragma unroll
    for (int i = 0; i < 4; i++)
#pragma unroll
        for (int j = 0; j < 4; j++)
#pragma unroll
            for (int r = 0; r < 4; r++) acc[i][j][r] = 0.f;

    auto load_tile = [&](int k0, int st) {
        uint32_t ab = aBase + st * STG;
        uint32_t bb = bBase + st * STG;
#pragma unroll
        for (int i = 0; i < 2; i++) {
            int id = i * 256 + tid;
            int r = id >> 2, c = id & 3;
            cp16(ab + r * 80 + c * 16, A + (size_t)(m0 + r) * lda + k0 + c * 8);
            cp16(bb + r * 80 + c * 16, B + (size_t)(n0 + r) * ldb + k0 + c * 8);
        }
        asm volatile("cp.async.commit_group;" ::: "memory");
    };

    const int T = K / 32;
    load_tile(0, 0);
    if (T > 1) load_tile(32, 1);

    for (int tt = 0; tt < T; tt++) {
        if (tt + 2 < T) asm volatile("cp.async.wait_group 1;" ::: "memory");
        else            asm volatile("cp.async.wait_group 0;" ::: "memory");
        __syncthreads();

        // issue next stage load FIRST so LDG overlaps compute below
        if (tt + 2 < T) load_tile((tt + 2) * 32, (tt + 2) % 3);

        const int st = tt % 3;
        const uint32_t sa = aBase + st * STG;
        const uint32_t sb = bBase + st * STG;

#pragma unroll
        for (int kk = 0; kk < 2; kk++) {
            uint32_t af[4][4], bf[4][2];
#pragma unroll
            for (int im = 0; im < 4; im++)
                ldsm4(af[im][0], af[im][1], af[im][2], af[im][3],
                      sa + aOff + im * 1280 + kk * 32);
#pragma unroll
            for (int p = 0; p < 2; p++)
                ldsm4(bf[2 * p][0], bf[2 * p][1], bf[2 * p + 1][0], bf[2 * p + 1][1],
                      sb + bOff + p * 1280 + kk * 32);
#pragma unroll
            for (int im = 0; im < 4; im++)
#pragma unroll
                for (int in = 0; in < 4; in++) {
                    asm volatile(
                        "mma.sync.aligned.m16n8k16.row.col.f32.f16.f16.f32 "
                        "{%0,%1,%2,%3},{%4,%5,%6,%7},{%8,%9},{%0,%1,%2,%3};\n"
                        : "+f"(acc[im][in][0]), "+f"(acc[im][in][1]),
                          "+f"(acc[im][in][2]), "+f"(acc[im][in][3])
                        : "r"(af[im][0]), "r"(af[im][1]), "r"(af[im][2]), "r"(af[im][3]),
                          "r"(bf[in][0]), "r"(bf[in][1]));
                }
        }
    }

    // epilogue
    const bool isv = KV && (m0 >= 512);
#pragma unroll
    for (int im = 0; im < 4; im++) {
        int r0 = m0 + wm + im * 16 + g;
        int r1 = r0 + 8;
        float bv0 = HAS_BIAS ? bias[r0] : 0.f;
        float bv1 = HAS_BIAS ? bias[r1] : 0.f;
        float2 st0;
        float w0, b0, w1, b1;
        if (RESX) {
            st0 = stats[blockIdx.z * NGRP + (r0 >> 5)];   // r0, r1 same 32-ch group
            w0 = resw[r0] * st0.y; b0 = resb[r0] - st0.x * w0;
            w1 = resw[r1] * st0.y; b1 = resb[r1] - st0.x * w1;
        }
#pragma unroll
        for (int in = 0; in < 4; in++) {
            int c0 = n0 + wn + in * 8 + 2 * t;
            float v0 = acc[im][in][0] + bv0;
            float v1 = acc[im][in][1] + bv0;
            float v2 = acc[im][in][2] + bv1;
            float v3 = acc[im][in][3] + bv1;
            if (C_HALF || isv) {
                __half* C16 = (C_HALF ? (__half*)Cv + (size_t)blockIdx.z * sC
                                      : C2 + (size_t)blockIdx.z * sC2);
                int rr0 = isv ? r0 - 512 : r0;
                int rr1 = isv ? r1 - 512 : r1;
                *reinterpret_cast<__half2*>(&C16[(size_t)rr0 * ldc + c0]) = __floats2half2_rn(v0, v1);
                *reinterpret_cast<__half2*>(&C16[(size_t)rr1 * ldc + c0]) = __floats2half2_rn(v2, v3);
            } else {
                float* C = (float*)Cv + (size_t)blockIdx.z * sC;
                if (RESX) {
                    float2 x0 = *reinterpret_cast<const float2*>(&resx[(size_t)r0 * ldc + c0]);
                    float2 x1 = *reinterpret_cast<const float2*>(&resx[(size_t)r1 * ldc + c0]);
                    v0 += x0.x * w0 + b0; v1 += x0.y * w0 + b0;
                    v2 += x1.x * w1 + b1; v3 += x1.y * w1 + b1;
                }
                *reinterpret_cast<float2*>(&C[(size_t)r0 * ldc + c0]) = make_float2(v0, v1);
                *reinterpret_cast<float2*>(&C[(size_t)r1 * ldc + c0]) = make_float2(v2, v3);
            }
        }
    }
}

// ---------------------------------------------------------------------------
extern "C" void kernel_launch(void* const* d_in, const int* in_sizes, int n_in,
                              void* d_out, int out_size)
{
    const float* x   = (const float*)d_in[0];
    const float* n1w = (const float*)d_in[1];
    const float* n1b = (const float*)d_in[2];
    const float* kvw = (const float*)d_in[3];
    const float* kvb = (const float*)d_in[4];
    const float* n2w = (const float*)d_in[5];
    const float* n2b = (const float*)d_in[6];
    const float* ow  = (const float*)d_in[7];
    const float* ob  = (const float*)d_in[8];
    float* out = (float*)d_out;

    float *kf;
    float2* stats;
    __half *o116, *xnT16, *v16, *k16, *qT16, *hT16, *ctx16, *w16;
    cudaGetSymbolAddress((void**)&kf,    g_k);
    cudaGetSymbolAddress((void**)&o116,  g_o116);
    cudaGetSymbolAddress((void**)&xnT16, g_xnT16);
    cudaGetSymbolAddress((void**)&v16,   g_v16);
    cudaGetSymbolAddress((void**)&k16,   g_k16);
    cudaGetSymbolAddress((void**)&qT16,  g_qT16);
    cudaGetSymbolAddress((void**)&hT16,  g_hT16);
    cudaGetSymbolAddress((void**)&ctx16, g_ctx16);
    cudaGetSymbolAddress((void**)&stats, g_stats);
    cudaGetSymbolAddress((void**)&w16,   g_w16);

    __half* kvw16 = w16;
    __half* ow16  = w16 + 1024 * 512;

    const size_t sXN  = (size_t)CCH * NSP;
    const size_t sCTX = (size_t)CCH * CCH;

    // 0. weight converts (tiny)
    cvt16<<<256, 256>>>(kvw, kvw16, (1024 * 512) / 4);
    cvt16<<<128, 256>>>(ow,  ow16,  (512 * 512) / 4);

    // 1. GroupNorm1 -> xnT16 + stats (no fp32 xn materialized)
    gnT<float><<<BATCH * NGRP, 256>>>(x, n1w, n1b, xnT16, stats, 0);

    // 2. kv GEMM: k (fp32) + v16 (fp16) split epilogue. M=1024,N=4096,K=512
    gemm_fp16<true, false, true, false><<<dim3(NSP / 128, 1024 / 128, BATCH), 256>>>(
        kvw16, xnT16, kf, v16, kvb, nullptr, nullptr, nullptr, nullptr,
        CCH, CCH, NSP, CCH, 0, sXN, sXN, sXN);

    // 3. channel softmax -> qT16 ; spatial softmax -> k16
    softmax_chT<<<dim3(NSP / 128, BATCH), 128>>>(kf, qT16, 0.044194173824159216f);
    softmax_spT<<<BATCH * CCH, 256>>>(kf, k16);

    // 4. ctx2[e,d] = sum_n v[e,n]*k[d,n]  (M=512,N=512,K=4096) -> fp16
    gemm_fp16<false, true, false, false><<<dim3(CCH / 128, CCH / 128, BATCH), 256>>>(
        v16, k16, ctx16, nullptr, nullptr, nullptr, nullptr, nullptr, nullptr,
        NSP, NSP, CCH, NSP, sXN, sXN, sCTX, 0);

    // 5. o1[e,n] = sum_d ctx2[e,d]*qT[n,d]  (M=512,N=4096,K=512) -> fp16
    gemm_fp16<false, true, false, false><<<dim3(NSP / 128, CCH / 128, BATCH), 256>>>(
        ctx16, qT16, o116, nullptr, nullptr, nullptr, nullptr, nullptr, nullptr,
        CCH, CCH, NSP, CCH, sCTX, sXN, sXN, 0);

    // 6. h = gelu(GN2(o1)) -> hT16 (fp16 input)
    gnT<__half><<<BATCH * NGRP, 256>>>(o116, n2w, n2b, hT16, nullptr, 1);

    // 7. out = W_out @ h + b_out + gn1(x) (residual recomputed from x + stats)
    gemm_fp16<false, false, true, true><<<dim3(NSP / 128, CCH / 128, BATCH), 256>>>(
        ow16, hT16, out, nullptr, ob, x, stats, n1w, n1b,
        CCH, CCH, NSP, CCH, 0, sXN, sXN, 0);
}

// round 9
// speedup vs baseline: 5.2326x; 1.1064x over previous
#include <cuda_runtime.h>
#include <cuda_fp16.h>
#include <math.h>
#include <stdint.h>

#define BATCH 16
#define CCH   512
#define NSP   4096
#define NGRP  16

// Scratch (device globals: allocation-free per harness rules)
__device__ float  g_k  [(size_t)BATCH * CCH * NSP];   // k fp32 (pre-softmax)
__device__ __half g_o116[(size_t)BATCH * CCH * NSP];  // attention output fp16
__device__ __half g_xnT16[(size_t)BATCH * CCH * NSP]; // xn^T [n][c]
__device__ __half g_v16 [(size_t)BATCH * CCH * NSP];  // v fp16 [e][n]
__device__ __half g_E16 [(size_t)BATCH * CCH * NSP];  // exp(k) fp16 [d][n]
__device__ __half g_qT16[(size_t)BATCH * CCH * NSP];  // q^T [n][d]
__device__ __half g_hT16[(size_t)BATCH * CCH * NSP];  // h^T [n][c]
__device__ __half g_ctx16[(size_t)BATCH * CCH * CCH]; // ctx2 [e][d]
__device__ float  g_rsinv[BATCH * CCH];               // 1 / spatial rowsum per (b,d)
__device__ float  g_csinv[BATCH * NSP];               // scale / channel colsum per (b,n)
__device__ float2 g_stats[BATCH * NGRP];              // gn1 (mean, inv)
__device__ __half g_w16 [1024 * 512 + 512 * 512];     // kvw16, ow16

// ---------------------------------------------------------------------------
__device__ __forceinline__ uint32_t smem_u32(const void* p) {
    uint32_t a;
    asm("{ .reg .u64 t; cvta.to.shared.u64 t, %1; cvt.u32.u64 %0, t; }" : "=r"(a) : "l"(p));
    return a;
}
__device__ __forceinline__ void cp16(uint32_t dst, const void* src) {
    asm volatile("cp.async.cg.shared.global [%0], [%1], 16;" :: "r"(dst), "l"(src) : "memory");
}
__device__ __forceinline__ void ldsm4(uint32_t& r0, uint32_t& r1, uint32_t& r2, uint32_t& r3,
                                      uint32_t addr) {
    asm volatile("ldmatrix.sync.aligned.m8n8.x4.shared.b16 {%0,%1,%2,%3}, [%4];"
                 : "=r"(r0), "=r"(r1), "=r"(r2), "=r"(r3) : "r"(addr));
}
__device__ __forceinline__ float ldf(const float* p)  { return *p; }
__device__ __forceinline__ float ldf(const __half* p) { return __half2float(*p); }

// vectorized stats accumulation
__device__ __forceinline__ void stat_loop(const float* x, size_t base, int tid,
                                          float& s, float& s2) {
    const float4* p = (const float4*)(x + base);
    for (int i = tid; i < (32 * NSP) / 4; i += 256) {
        float4 v = p[i];
        s  += v.x + v.y + v.z + v.w;
        s2 += v.x * v.x + v.y * v.y + v.z * v.z + v.w * v.w;
    }
}
__device__ __forceinline__ void stat_loop(const __half* x, size_t base, int tid,
                                          float& s, float& s2) {
    const uint4* p = (const uint4*)(x + base);
    for (int i = tid; i < (32 * NSP) / 8; i += 256) {
        uint4 u = p[i];
        float2 fa = __half22float2(*(__half2*)&u.x);
        float2 fb = __half22float2(*(__half2*)&u.y);
        float2 fc = __half22float2(*(__half2*)&u.z);
        float2 fd = __half22float2(*(__half2*)&u.w);
        s  += fa.x + fa.y + fb.x + fb.y + fc.x + fc.y + fd.x + fd.y;
        s2 += fa.x * fa.x + fa.y * fa.y + fb.x * fb.x + fb.y * fb.y +
              fc.x * fc.x + fc.y * fc.y + fd.x * fd.x + fd.y * fd.y;
    }
}

// ---------------------------------------------------------------------------
// GroupNorm (+optional exact GELU) -> transposed fp16 output only.
// ---------------------------------------------------------------------------
template <typename Tin>
__global__ void gnT(const Tin* __restrict__ x, const float* __restrict__ w,
                    const float* __restrict__ b, __half* __restrict__ yT16,
                    float2* __restrict__ stats, int gelu)
{
    const int GE = 32 * NSP;
    const int blk = blockIdx.x;
    const int bb = blk >> 4;
    const int cbase = (blk & 15) << 5;
    const size_t base = (size_t)blk * GE;
    const int tid = threadIdx.x;

    float s = 0.f, s2 = 0.f;
    stat_loop(x, base, tid, s, s2);
    __shared__ float sh1[256], sh2[256];
    sh1[tid] = s; sh2[tid] = s2;
    __syncthreads();
    for (int o = 128; o > 0; o >>= 1) {
        if (tid < o) { sh1[tid] += sh1[tid + o]; sh2[tid] += sh2[tid + o]; }
        __syncthreads();
    }
    float mean = sh1[0] / (float)GE;
    float var  = sh2[0] / (float)GE - mean * mean;
    float inv  = rsqrtf(var + 1e-5f);
    if (stats && tid == 0) stats[blk] = make_float2(mean, inv);

    __shared__ float sm[32][33];
    const int tx = tid & 31, ty = tid >> 5;
    __half* yT = yT16 + (size_t)bb * NSP * CCH;

    for (int n0 = 0; n0 < NSP; n0 += 32) {
#pragma unroll
        for (int i = 0; i < 4; i++) {
            int c = ty + i * 8;
            float v = ldf(&x[base + (size_t)c * NSP + n0 + tx]);
            v = (v - mean) * inv * w[cbase + c] + b[cbase + c];
            if (gelu) v = 0.5f * v * (1.0f + erff(v * 0.70710678118654752f));
            sm[tx][c] = v;
        }
        __syncthreads();
#pragma unroll
        for (int i = 0; i < 4; i++) {
            int j = ty + i * 8;
            yT[(size_t)(n0 + j) * CCH + cbase + tx] = __float2half(sm[j][tx]);
        }
        __syncthreads();
    }
}

// ---------------------------------------------------------------------------
// E = exp(k) fp16 + inverse spatial rowsum. One block per (b,d) row.
// No max subtraction: |k| <= ~6 (unit-variance GN through 1/sqrt(C) conv),
// exp(k) <= ~400 << fp16 max. Rowsum accumulated from the fp16-rounded E
// so softmax rows sum to exactly 1 in the quantized domain.
// ---------------------------------------------------------------------------
__global__ void expk(const float* __restrict__ kf, __half* __restrict__ E,
                     float* __restrict__ rsinv)
{
    const size_t off = (size_t)blockIdx.x * NSP;
    const float4* p4 = (const float4*)(kf + off);
    __half* o = E + off;
    const int tid = threadIdx.x;

    float s = 0.f;
    for (int i = tid; i < NSP / 4; i += 256) {
        float4 v = p4[i];
        __half2 h0 = __floats2half2_rn(__expf(v.x), __expf(v.y));
        __half2 h1 = __floats2half2_rn(__expf(v.z), __expf(v.w));
        *(__half2*)&o[4 * i]     = h0;
        *(__half2*)&o[4 * i + 2] = h1;
        float2 f0 = __half22float2(h0), f1 = __half22float2(h1);
        s += f0.x + f0.y + f1.x + f1.y;
    }
    __shared__ float sh[256];
    sh[tid] = s; __syncthreads();
    for (int o2 = 128; o2 > 0; o2 >>= 1) {
        if (tid < o2) sh[tid] += sh[tid + o2];
        __syncthreads();
    }
    if (tid == 0) rsinv[blockIdx.x] = 1.0f / sh[0];
}

// ---------------------------------------------------------------------------
// Channel colsum of E16: csinv[b][n] = scale / sum_d E[d][n].
// One block per (b, 512-n chunk); thread owns 2 columns.
// ---------------------------------------------------------------------------
__global__ void colsum(const __half* __restrict__ E, float* __restrict__ csinv,
                       float scale)
{
    const int bb = blockIdx.x >> 3;
    const int n0 = (blockIdx.x & 7) * 512;
    const __half* p = E + (size_t)bb * CCH * NSP + n0 + 2 * threadIdx.x;
    float s0 = 0.f, s1 = 0.f;
    for (int d = 0; d < CCH; d++) {
        float2 f = __half22float2(*(const __half2*)&p[(size_t)d * NSP]);
        s0 += f.x; s1 += f.y;
    }
    float* c = csinv + bb * NSP + n0 + 2 * threadIdx.x;
    c[0] = scale / s0;
    c[1] = scale / s1;
}

// ---------------------------------------------------------------------------
// qT[n][d] = E[d][n] * csinv[n]  (transposed normalize, exp-free).
// ---------------------------------------------------------------------------
__global__ __launch_bounds__(128)
void qTn(const __half* __restrict__ E, const float* __restrict__ csinv,
         __half* __restrict__ qT)
{
    const int bb = blockIdx.y;
    const int nb = blockIdx.x * 128;
    const int tid = threadIdx.x;
    const __half* kp = E + (size_t)bb * CCH * NSP + nb + tid;
    const float invc = csinv[bb * NSP + nb + tid];

    __shared__ __half sm[128][66];
    __half* qb = qT + (size_t)bb * NSP * CCH;
    const int lane = tid & 31, wrp = tid >> 5;

    for (int c0 = 0; c0 < CCH; c0 += 64) {
#pragma unroll 8
        for (int cc = 0; cc < 64; cc++)
            sm[tid][cc] = __float2half(__half2float(kp[(size_t)(c0 + cc) * NSP]) * invc);
        __syncthreads();
#pragma unroll
        for (int it = 0; it < 32; it++) {
            int nl = it * 4 + wrp;
            *(__half2*)&qb[(size_t)(nb + nl) * CCH + c0 + 2 * lane] =
                *(const __half2*)&sm[nl][2 * lane];
        }
        __syncthreads();
    }
}

// ---------------------------------------------------------------------------
// Flat fp32 -> fp16 convert (weights only).
// ---------------------------------------------------------------------------
__global__ void cvt16(const float* __restrict__ in, __half* __restrict__ out, size_t n4)
{
    size_t stride = (size_t)gridDim.x * blockDim.x;
    const float4* in4 = (const float4*)in;
    __half2* o2 = (__half2*)out;
    for (size_t i = (size_t)blockIdx.x * blockDim.x + threadIdx.x; i < n4; i += stride) {
        float4 v = in4[i];
        o2[2 * i]     = __floats2half2_rn(v.x, v.y);
        o2[2 * i + 1] = __floats2half2_rn(v.z, v.w);
    }
}

// ---------------------------------------------------------------------------
// fp16 mma.sync (m16n8k16) GEMM, 3-stage cp.async, ldmatrix fragments.
// C[m,n] = sum_k A[m,k]*B[n,k]  (+bias[m]) (+residual) (*cscale[n])
// RESX: residual recomputed from raw x via gn1 stats.
// CSCALE: per-output-column scale (spatial-softmax normalization fold).
// Block 128x128x32, 256 threads = 8 warps (2m x 4n), warp tile 64x32.
// ---------------------------------------------------------------------------
#define STG 10240

template <bool KV, bool C_HALF, bool HAS_BIAS, bool RESX, bool CSCALE>
__global__ __launch_bounds__(256, 2)
void gemm_fp16(const __half* __restrict__ A, const __half* __restrict__ B,
               void* __restrict__ Cv, __half* __restrict__ C2,
               const float* __restrict__ bias,
               const float* __restrict__ resx, const float2* __restrict__ stats,
               const float* __restrict__ resw, const float* __restrict__ resb,
               const float* __restrict__ cscale,
               int lda, int ldb, int ldc, int K,
               size_t sA, size_t sB, size_t sC, size_t sC2)
{
    __shared__ __half As[3][128 * 40];
    __shared__ __half Bs[3][128 * 40];

    A += (size_t)blockIdx.z * sA;
    B += (size_t)blockIdx.z * sB;
    if (RESX)   resx   += (size_t)blockIdx.z * sC;
    if (CSCALE) cscale += (size_t)blockIdx.z * CCH;

    const int tid  = threadIdx.x;
    const int lane = tid & 31;
    const int warp = tid >> 5;
    const int g = lane >> 2;
    const int t = lane & 3;
    const int wm = (warp & 1) * 64;
    const int wn = (warp >> 1) * 32;
    const int m0 = blockIdx.y * 128;
    const int n0 = blockIdx.x * 128;

    const uint32_t aBase = smem_u32(As);
    const uint32_t bBase = smem_u32(Bs);

    const uint32_t aOff = (uint32_t)(wm + (lane & 15)) * 80 + (lane >> 4) * 16;
    const uint32_t bOff = (uint32_t)(wn + (lane & 7) + ((lane >> 4) << 3)) * 80 +
                          ((lane >> 3) & 1) * 16;

    float acc[4][4][4];
#pragma unroll
    for (int i = 0; i < 4; i++)
#pragma unroll
        for (int j = 0; j < 4; j++)
#pragma unroll
            for (int r = 0; r < 4; r++) acc[i][j][r] = 0.f;

    auto load_tile = [&](int k0, int st) {
        uint32_t ab = aBase + st * STG;
        uint32_t bb = bBase + st * STG;
#pragma unroll
        for (int i = 0; i < 2; i++) {
            int id = i * 256 + tid;
            int r = id >> 2, c = id & 3;
            cp16(ab + r * 80 + c * 16, A + (size_t)(m0 + r) * lda + k0 + c * 8);
            cp16(bb + r * 80 + c * 16, B + (size_t)(n0 + r) * ldb + k0 + c * 8);
        }
        asm volatile("cp.async.commit_group;" ::: "memory");
    };

    const int T = K / 32;
    load_tile(0, 0);
    if (T > 1) load_tile(32, 1);

    for (int tt = 0; tt < T; tt++) {
        if (tt + 2 < T) asm volatile("cp.async.wait_group 1;" ::: "memory");
        else            asm volatile("cp.async.wait_group 0;" ::: "memory");
        __syncthreads();

        if (tt + 2 < T) load_tile((tt + 2) * 32, (tt + 2) % 3);

        const int st = tt % 3;
        const uint32_t sa = aBase + st * STG;
        const uint32_t sb = bBase + st * STG;

#pragma unroll
        for (int kk = 0; kk < 2; kk++) {
            uint32_t af[4][4], bf[4][2];
#pragma unroll
            for (int im = 0; im < 4; im++)
                ldsm4(af[im][0], af[im][1], af[im][2], af[im][3],
                      sa + aOff + im * 1280 + kk * 32);
#pragma unroll
            for (int p = 0; p < 2; p++)
                ldsm4(bf[2 * p][0], bf[2 * p][1], bf[2 * p + 1][0], bf[2 * p + 1][1],
                      sb + bOff + p * 1280 + kk * 32);
#pragma unroll
            for (int im = 0; im < 4; im++)
#pragma unroll
                for (int in = 0; in < 4; in++) {
                    asm volatile(
                        "mma.sync.aligned.m16n8k16.row.col.f32.f16.f16.f32 "
                        "{%0,%1,%2,%3},{%4,%5,%6,%7},{%8,%9},{%0,%1,%2,%3};\n"
                        : "+f"(acc[im][in][0]), "+f"(acc[im][in][1]),
                          "+f"(acc[im][in][2]), "+f"(acc[im][in][3])
                        : "r"(af[im][0]), "r"(af[im][1]), "r"(af[im][2]), "r"(af[im][3]),
                          "r"(bf[in][0]), "r"(bf[in][1]));
                }
        }
    }

    // epilogue
    const bool isv = KV && (m0 >= 512);
#pragma unroll
    for (int im = 0; im < 4; im++) {
        int r0 = m0 + wm + im * 16 + g;
        int r1 = r0 + 8;
        float bv0 = HAS_BIAS ? bias[r0] : 0.f;
        float bv1 = HAS_BIAS ? bias[r1] : 0.f;
        float w0, b0, w1, b1;
        if (RESX) {
            float2 st0 = stats[blockIdx.z * NGRP + (r0 >> 5)];
            w0 = resw[r0] * st0.y; b0 = resb[r0] - st0.x * w0;
            w1 = resw[r1] * st0.y; b1 = resb[r1] - st0.x * w1;
        }
#pragma unroll
        for (int in = 0; in < 4; in++) {
            int c0 = n0 + wn + in * 8 + 2 * t;
            float v0 = acc[im][in][0] + bv0;
            float v1 = acc[im][in][1] + bv0;
            float v2 = acc[im][in][2] + bv1;
            float v3 = acc[im][in][3] + bv1;
            if (CSCALE) {
                float2 cs = *reinterpret_cast<const float2*>(&cscale[c0]);
                v0 *= cs.x; v1 *= cs.y; v2 *= cs.x; v3 *= cs.y;
            }
            if (C_HALF || isv) {
                __half* C16 = (C_HALF ? (__half*)Cv + (size_t)blockIdx.z * sC
                                      : C2 + (size_t)blockIdx.z * sC2);
                int rr0 = isv ? r0 - 512 : r0;
                int rr1 = isv ? r1 - 512 : r1;
                *reinterpret_cast<__half2*>(&C16[(size_t)rr0 * ldc + c0]) = __floats2half2_rn(v0, v1);
                *reinterpret_cast<__half2*>(&C16[(size_t)rr1 * ldc + c0]) = __floats2half2_rn(v2, v3);
            } else {
                float* C = (float*)Cv + (size_t)blockIdx.z * sC;
                if (RESX) {
                    float2 x0 = *reinterpret_cast<const float2*>(&resx[(size_t)r0 * ldc + c0]);
                    float2 x1 = *reinterpret_cast<const float2*>(&resx[(size_t)r1 * ldc + c0]);
                    v0 += x0.x * w0 + b0; v1 += x0.y * w0 + b0;
                    v2 += x1.x * w1 + b1; v3 += x1.y * w1 + b1;
                }
                *reinterpret_cast<float2*>(&C[(size_t)r0 * ldc + c0]) = make_float2(v0, v1);
                *reinterpret_cast<float2*>(&C[(size_t)r1 * ldc + c0]) = make_float2(v2, v3);
            }
        }
    }
}

// ---------------------------------------------------------------------------
extern "C" void kernel_launch(void* const* d_in, const int* in_sizes, int n_in,
                              void* d_out, int out_size)
{
    const float* x   = (const float*)d_in[0];
    const float* n1w = (const float*)d_in[1];
    const float* n1b = (const float*)d_in[2];
    const float* kvw = (const float*)d_in[3];
    const float* kvb = (const float*)d_in[4];
    const float* n2w = (const float*)d_in[5];
    const float* n2b = (const float*)d_in[6];
    const float* ow  = (const float*)d_in[7];
    const float* ob  = (const float*)d_in[8];
    float* out = (float*)d_out;

    float *kf, *rsinv, *csinv;
    float2* stats;
    __half *o116, *xnT16, *v16, *E16, *qT16, *hT16, *ctx16, *w16;
    cudaGetSymbolAddress((void**)&kf,    g_k);
    cudaGetSymbolAddress((void**)&o116,  g_o116);
    cudaGetSymbolAddress((void**)&xnT16, g_xnT16);
    cudaGetSymbolAddress((void**)&v16,   g_v16);
    cudaGetSymbolAddress((void**)&E16,   g_E16);
    cudaGetSymbolAddress((void**)&qT16,  g_qT16);
    cudaGetSymbolAddress((void**)&hT16,  g_hT16);
    cudaGetSymbolAddress((void**)&ctx16, g_ctx16);
    cudaGetSymbolAddress((void**)&rsinv, g_rsinv);
    cudaGetSymbolAddress((void**)&csinv, g_csinv);
    cudaGetSymbolAddress((void**)&stats, g_stats);
    cudaGetSymbolAddress((void**)&w16,   g_w16);

    __half* kvw16 = w16;
    __half* ow16  = w16 + 1024 * 512;

    const size_t sXN  = (size_t)CCH * NSP;
    const size_t sCTX = (size_t)CCH * CCH;

    // 0. weight converts (tiny)
    cvt16<<<256, 256>>>(kvw, kvw16, (1024 * 512) / 4);
    cvt16<<<128, 256>>>(ow,  ow16,  (512 * 512) / 4);

    // 1. GroupNorm1 -> xnT16 + stats
    gnT<float><<<BATCH * NGRP, 256>>>(x, n1w, n1b, xnT16, stats, 0);

    // 2. kv GEMM: k (fp32) + v16 (fp16) split epilogue
    gemm_fp16<true, false, true, false, false><<<dim3(NSP / 128, 1024 / 128, BATCH), 256>>>(
        kvw16, xnT16, kf, v16, kvb, nullptr, nullptr, nullptr, nullptr, nullptr,
        CCH, CCH, NSP, CCH, 0, sXN, sXN, sXN);

    // 3. E = exp(k) fp16 + rowsum-inv; colsum-inv; qT normalize
    expk<<<BATCH * CCH, 256>>>(kf, E16, rsinv);
    colsum<<<BATCH * 8, 256>>>(E16, csinv, 0.044194173824159216f);
    qTn<<<dim3(NSP / 128, BATCH), 128>>>(E16, csinv, qT16);

    // 4. ctx2[e,d] = (sum_n v[e,n]*E[d,n]) * rsinv[d]  -> fp16 (CSCALE fold)
    gemm_fp16<false, true, false, false, true><<<dim3(CCH / 128, CCH / 128, BATCH), 256>>>(
        v16, E16, ctx16, nullptr, nullptr, nullptr, nullptr, nullptr, nullptr, rsinv,
        NSP, NSP, CCH, NSP, sXN, sXN, sCTX, 0);

    // 5. o1[e,n] = sum_d ctx2[e,d]*qT[n,d] -> fp16
    gemm_fp16<false, true, false, false, false><<<dim3(NSP / 128, CCH / 128, BATCH), 256>>>(
        ctx16, qT16, o116, nullptr, nullptr, nullptr, nullptr, nullptr, nullptr, nullptr,
        CCH, CCH, NSP, CCH, sCTX, sXN, sXN, 0);

    // 6. h = gelu(GN2(o1)) -> hT16
    gnT<__half><<<BATCH * NGRP, 256>>>(o116, n2w, n2b, hT16, nullptr, 1);

    // 7. out = W_out @ h + b_out + gn1(x)
    gemm_fp16<false, false, true, true, false><<<dim3(NSP / 128, CCH / 128, BATCH), 256>>>(
        ow16, hT16, out, nullptr, ob, x, stats, n1w, n1b, nullptr,
        CCH, CCH, NSP, CCH, 0, sXN, sXN, 0);
}

// round 10
// speedup vs baseline: 6.9507x; 1.3283x over previous
#include <cuda_runtime.h>
#include <cuda_fp16.h>
#include <math.h>
#include <stdint.h>

#define BATCH 16
#define CCH   512
#define NSP   4096
#define NGRP  16

// Scratch (device globals: allocation-free per harness rules)
__device__ float  g_k  [(size_t)BATCH * CCH * NSP];   // k fp32 (pre-softmax)
__device__ __half g_o116[(size_t)BATCH * CCH * NSP];  // attention output fp16 [e][n]
__device__ __half g_xn16[(size_t)BATCH * CCH * NSP];  // gn1(x) fp16 [c][n]
__device__ __half g_v16 [(size_t)BATCH * CCH * NSP];  // v fp16 [e][n]
__device__ __half g_E16 [(size_t)BATCH * CCH * NSP];  // exp(k) fp16 [d][n]
__device__ __half g_h16 [(size_t)BATCH * CCH * NSP];  // gelu(gn2(o1)) fp16 [c][n]
__device__ __half g_ctx16[(size_t)BATCH * CCH * CCH]; // ctx2 [e][d]
__device__ float  g_rsinv[BATCH * CCH];               // 1 / spatial rowsum
__device__ float  g_csinv[BATCH * NSP];               // scale / channel colsum
__device__ float2 g_part [BATCH * NGRP * 8];          // partial gn stats
__device__ float2 g_stats1[BATCH * NGRP];             // gn1 (mean, inv)
__device__ float2 g_stats2[BATCH * NGRP];             // gn2 (mean, inv)
__device__ __half g_w16 [1024 * 512 + 512 * 512];     // kvw16, ow16

// ---------------------------------------------------------------------------
__device__ __forceinline__ uint32_t smem_u32(const void* p) {
    uint32_t a;
    asm("{ .reg .u64 t; cvta.to.shared.u64 t, %1; cvt.u32.u64 %0, t; }" : "=r"(a) : "l"(p));
    return a;
}
__device__ __forceinline__ void cp16(uint32_t dst, const void* src) {
    asm volatile("cp.async.cg.shared.global [%0], [%1], 16;" :: "r"(dst), "l"(src) : "memory");
}
__device__ __forceinline__ void ldsm4(uint32_t& r0, uint32_t& r1, uint32_t& r2, uint32_t& r3,
                                      uint32_t addr) {
    asm volatile("ldmatrix.sync.aligned.m8n8.x4.shared.b16 {%0,%1,%2,%3}, [%4];"
                 : "=r"(r0), "=r"(r1), "=r"(r2), "=r"(r3) : "r"(addr));
}
__device__ __forceinline__ void ldsm4t(uint32_t& r0, uint32_t& r1, uint32_t& r2, uint32_t& r3,
                                       uint32_t addr) {
    asm volatile("ldmatrix.sync.aligned.m8n8.x4.trans.shared.b16 {%0,%1,%2,%3}, [%4];"
                 : "=r"(r0), "=r"(r1), "=r"(r2), "=r"(r3) : "r"(addr));
}

// ---------------------------------------------------------------------------
// GroupNorm stage 1: partial (sum, sumsq). Block = (group, n-chunk of 512).
// ---------------------------------------------------------------------------
__global__ void gstats32(const float* __restrict__ x, float2* __restrict__ part)
{
    const int bx = blockIdx.x;
    const size_t base = (size_t)(bx >> 3) * 32 * NSP + (size_t)(bx & 7) * 512;
    const int tid = threadIdx.x;
    float s = 0.f, s2 = 0.f;
#pragma unroll 4
    for (int i = 0; i < 16; i++) {
        int id = i * 256 + tid;
        int r = id >> 7, c4 = id & 127;
        float4 v = *(const float4*)(x + base + (size_t)r * NSP + c4 * 4);
        s  += v.x + v.y + v.z + v.w;
        s2 += v.x * v.x + v.y * v.y + v.z * v.z + v.w * v.w;
    }
    __shared__ float sh1[256], sh2[256];
    sh1[tid] = s; sh2[tid] = s2;
    __syncthreads();
    for (int o = 128; o > 0; o >>= 1) {
        if (tid < o) { sh1[tid] += sh1[tid + o]; sh2[tid] += sh2[tid + o]; }
        __syncthreads();
    }
    if (tid == 0) part[bx] = make_float2(sh1[0], sh2[0]);
}

__global__ void gstats16(const __half* __restrict__ x, float2* __restrict__ part)
{
    const int bx = blockIdx.x;
    const size_t base = (size_t)(bx >> 3) * 32 * NSP + (size_t)(bx & 7) * 512;
    const int tid = threadIdx.x;
    float s = 0.f, s2 = 0.f;
#pragma unroll 4
    for (int i = 0; i < 8; i++) {
        int id = i * 256 + tid;
        int r = id >> 6, c8 = id & 63;
        uint4 u = *(const uint4*)(x + base + (size_t)r * NSP + c8 * 8);
        float2 fa = __half22float2(*(__half2*)&u.x);
        float2 fb = __half22float2(*(__half2*)&u.y);
        float2 fc = __half22float2(*(__half2*)&u.z);
        float2 fd = __half22float2(*(__half2*)&u.w);
        s  += fa.x + fa.y + fb.x + fb.y + fc.x + fc.y + fd.x + fd.y;
        s2 += fa.x * fa.x + fa.y * fa.y + fb.x * fb.x + fb.y * fb.y +
              fc.x * fc.x + fc.y * fc.y + fd.x * fd.x + fd.y * fd.y;
    }
    __shared__ float sh1[256], sh2[256];
    sh1[tid] = s; sh2[tid] = s2;
    __syncthreads();
    for (int o = 128; o > 0; o >>= 1) {
        if (tid < o) { sh1[tid] += sh1[tid + o]; sh2[tid] += sh2[tid + o]; }
        __syncthreads();
    }
    if (tid == 0) part[bx] = make_float2(sh1[0], sh2[0]);
}

// Stage 2: reduce 8 partials per group -> (mean, inv). One block, 256 threads.
__global__ void gred(const float2* __restrict__ part, float2* __restrict__ stats)
{
    int g = threadIdx.x;
    float s = 0.f, s2 = 0.f;
#pragma unroll
    for (int j = 0; j < 8; j++) {
        float2 p = part[g * 8 + j];
        s += p.x; s2 += p.y;
    }
    const float GE = 32.f * NSP;
    float mean = s / GE;
    float var  = s2 / GE - mean * mean;
    stats[g] = make_float2(mean, rsqrtf(var + 1e-5f));
}

// Stage 3: normalize (+gelu) -> fp16 same layout. Block = (group, n-chunk).
template <typename Tin, int GELU>
__global__ void gnorm(const Tin* __restrict__ x, const float* __restrict__ w,
                      const float* __restrict__ b, const float2* __restrict__ stats,
                      __half* __restrict__ y)
{
    const int bx = blockIdx.x;
    const int grp = bx >> 3;
    const int cbase = (grp & 15) << 5;
    const size_t base = (size_t)grp * 32 * NSP + (size_t)(bx & 7) * 512;
    const int tid = threadIdx.x;
    float2 st = stats[grp];

#pragma unroll 2
    for (int i = 0; i < 16; i++) {
        int id = i * 256 + tid;
        int r = id >> 7, c4 = id & 127;
        float sc = w[cbase + r] * st.y;
        float of = b[cbase + r] - st.x * sc;
        size_t off = base + (size_t)r * NSP + c4 * 4;
        float4 v;
        if (sizeof(Tin) == 4) {
            v = *(const float4*)((const float*)x + off);
        } else {
            uint2 u = *(const uint2*)((const __half*)x + off);
            float2 f0 = __half22float2(*(__half2*)&u.x);
            float2 f1 = __half22float2(*(__half2*)&u.y);
            v = make_float4(f0.x, f0.y, f1.x, f1.y);
        }
        v.x = v.x * sc + of; v.y = v.y * sc + of;
        v.z = v.z * sc + of; v.w = v.w * sc + of;
        if (GELU) {
            v.x = 0.5f * v.x * (1.0f + erff(v.x * 0.70710678f));
            v.y = 0.5f * v.y * (1.0f + erff(v.y * 0.70710678f));
            v.z = 0.5f * v.z * (1.0f + erff(v.z * 0.70710678f));
            v.w = 0.5f * v.w * (1.0f + erff(v.w * 0.70710678f));
        }
        __half2* o2 = (__half2*)(y + off);
        o2[0] = __floats2half2_rn(v.x, v.y);
        o2[1] = __floats2half2_rn(v.z, v.w);
    }
}

// ---------------------------------------------------------------------------
// E = exp(k) fp16 + inverse spatial rowsum. One block per (b,d) row.
// No max subtraction: |k| <= ~6 -> exp <= ~400 << fp16 max.
// ---------------------------------------------------------------------------
__global__ void expk(const float* __restrict__ kf, __half* __restrict__ E,
                     float* __restrict__ rsinv)
{
    const size_t off = (size_t)blockIdx.x * NSP;
    const float4* p4 = (const float4*)(kf + off);
    __half* o = E + off;
    const int tid = threadIdx.x;

    float s = 0.f;
    for (int i = tid; i < NSP / 4; i += 256) {
        float4 v = p4[i];
        __half2 h0 = __floats2half2_rn(__expf(v.x), __expf(v.y));
        __half2 h1 = __floats2half2_rn(__expf(v.z), __expf(v.w));
        *(__half2*)&o[4 * i]     = h0;
        *(__half2*)&o[4 * i + 2] = h1;
        float2 f0 = __half22float2(h0), f1 = __half22float2(h1);
        s += f0.x + f0.y + f1.x + f1.y;
    }
    __shared__ float sh[256];
    sh[tid] = s; __syncthreads();
    for (int o2 = 128; o2 > 0; o2 >>= 1) {
        if (tid < o2) sh[tid] += sh[tid + o2];
        __syncthreads();
    }
    if (tid == 0) rsinv[blockIdx.x] = 1.0f / sh[0];
}

// ---------------------------------------------------------------------------
// Channel colsum of E16: csinv[b][n] = scale / sum_d E[d][n].
// ---------------------------------------------------------------------------
__global__ void colsum(const __half* __restrict__ E, float* __restrict__ csinv,
                       float scale)
{
    const int bb = blockIdx.x >> 3;
    const int n0 = (blockIdx.x & 7) * 512;
    const __half* p = E + (size_t)bb * CCH * NSP + n0 + 2 * threadIdx.x;
    float s0 = 0.f, s1 = 0.f;
    for (int d = 0; d < CCH; d++) {
        float2 f = __half22float2(*(const __half2*)&p[(size_t)d * NSP]);
        s0 += f.x; s1 += f.y;
    }
    float* c = csinv + bb * NSP + n0 + 2 * threadIdx.x;
    c[0] = scale / s0;
    c[1] = scale / s1;
}

// ---------------------------------------------------------------------------
// Flat fp32 -> fp16 convert (weights only).
// ---------------------------------------------------------------------------
__global__ void cvt16(const float* __restrict__ in, __half* __restrict__ out, size_t n4)
{
    size_t stride = (size_t)gridDim.x * blockDim.x;
    const float4* in4 = (const float4*)in;
    __half2* o2 = (__half2*)out;
    for (size_t i = (size_t)blockIdx.x * blockDim.x + threadIdx.x; i < n4; i += stride) {
        float4 v = in4[i];
        o2[2 * i]     = __floats2half2_rn(v.x, v.y);
        o2[2 * i + 1] = __floats2half2_rn(v.z, v.w);
    }
}

// ---------------------------------------------------------------------------
// fp16 mma.sync (m16n8k16) GEMM, 3-stage cp.async, ldmatrix fragments.
// C[m,n] = sum_k A[m,k]*B(n,k)  (+bias[m]) (+residual) (*cscale[n])
// TB=0: B row-major [N][K]. TB=1: B K-major [K][N], loaded via ldmatrix.trans.
// RESX: residual recomputed from raw x via gn1 stats.
// CSCALE: per-output-column scale (stride csStride per batch).
// Block 128x128x32, 256 threads = 8 warps (2m x 4n), warp tile 64x32.
// ---------------------------------------------------------------------------
#define STGA 10240
#define STGBT 8704   // TB stage: 32 k-rows * 272B

template <bool KV, bool TB, bool C_HALF, bool HAS_BIAS, bool RESX, bool CSCALE>
__global__ __launch_bounds__(256, 2)
void gemm_fp16(const __half* __restrict__ A, const __half* __restrict__ B,
               void* __restrict__ Cv, __half* __restrict__ C2,
               const float* __restrict__ bias,
               const float* __restrict__ resx, const float2* __restrict__ stats,
               const float* __restrict__ resw, const float* __restrict__ resb,
               const float* __restrict__ cscale, int csStride,
               int lda, int ldb, int ldc, int K,
               size_t sA, size_t sB, size_t sC, size_t sC2)
{
    constexpr int BSTG = TB ? STGBT : STGA;
    __shared__ __half As[3 * STGA / 2];
    __shared__ __half Bs[3 * BSTG / 2];

    A += (size_t)blockIdx.z * sA;
    B += (size_t)blockIdx.z * sB;
    if (RESX)   resx   += (size_t)blockIdx.z * sC;
    if (CSCALE) cscale += (size_t)blockIdx.z * csStride;

    const int tid  = threadIdx.x;
    const int lane = tid & 31;
    const int warp = tid >> 5;
    const int g = lane >> 2;
    const int t = lane & 3;
    const int wm = (warp & 1) * 64;
    const int wn = (warp >> 1) * 32;
    const int m0 = blockIdx.y * 128;
    const int n0 = blockIdx.x * 128;

    const uint32_t aBase = smem_u32(As);
    const uint32_t bBase = smem_u32(Bs);

    const uint32_t aOff = (uint32_t)(wm + (lane & 15)) * 80 + (lane >> 4) * 16;
    // non-TB: row-major B fragment offsets
    const uint32_t bOff = (uint32_t)(wn + (lane & 7) + ((lane >> 4) << 3)) * 80 +
                          ((lane >> 3) & 1) * 16;
    // TB: trans tiles — tile=lane>>3: (kLo,nA),(kHi,nA),(kLo,nB),(kHi,nB)
    const uint32_t bOffT = (uint32_t)((lane & 7) + ((lane >> 3) & 1) * 8) * 272 +
                           (lane >> 4) * 16;

    float acc[4][4][4];
#pragma unroll
    for (int i = 0; i < 4; i++)
#pragma unroll
        for (int j = 0; j < 4; j++)
#pragma unroll
            for (int r = 0; r < 4; r++) acc[i][j][r] = 0.f;

    auto load_tile = [&](int k0, int st) {
        uint32_t ab = aBase + st * STGA;
        uint32_t bb = bBase + st * BSTG;
#pragma unroll
        for (int i = 0; i < 2; i++) {
            int id = i * 256 + tid;
            int r = id >> 2, c = id & 3;
            cp16(ab + r * 80 + c * 16, A + (size_t)(m0 + r) * lda + k0 + c * 8);
        }
#pragma unroll
        for (int i = 0; i < 2; i++) {
            int id = i * 256 + tid;
            if (TB) {
                int r = id >> 4, c = id & 15;   // 32 k-rows x 16 chunks
                cp16(bb + r * 272 + c * 16, B + (size_t)(k0 + r) * ldb + n0 + c * 8);
            } else {
                int r = id >> 2, c = id & 3;    // 128 n-rows x 4 chunks
                cp16(bb + r * 80 + c * 16, B + (size_t)(n0 + r) * ldb + k0 + c * 8);
            }
        }
        asm volatile("cp.async.commit_group;" ::: "memory");
    };

    const int T = K / 32;
    load_tile(0, 0);
    if (T > 1) load_tile(32, 1);

    for (int tt = 0; tt < T; tt++) {
        if (tt + 2 < T) asm volatile("cp.async.wait_group 1;" ::: "memory");
        else            asm volatile("cp.async.wait_group 0;" ::: "memory");
        __syncthreads();

        if (tt + 2 < T) load_tile((tt + 2) * 32, (tt + 2) % 3);

        const int st = tt % 3;
        const uint32_t sa = aBase + st * STGA;
        const uint32_t sb = bBase + st * BSTG;

#pragma unroll
        for (int kk = 0; kk < 2; kk++) {
            uint32_t af[4][4], bf[4][2];
#pragma unroll
            for (int im = 0; im < 4; im++)
                ldsm4(af[im][0], af[im][1], af[im][2], af[im][3],
                      sa + aOff + im * 1280 + kk * 32);
            if (TB) {
#pragma unroll
                for (int p = 0; p < 2; p++)
                    ldsm4t(bf[2 * p][0], bf[2 * p][1], bf[2 * p + 1][0], bf[2 * p + 1][1],
                           sb + bOffT + kk * 4352 + (wn + p * 16) * 2);
            } else {
#pragma unroll
                for (int p = 0; p < 2; p++)
                    ldsm4(bf[2 * p][0], bf[2 * p][1], bf[2 * p + 1][0], bf[2 * p + 1][1],
                          sb + bOff + p * 1280 + kk * 32);
            }
#pragma unroll
            for (int im = 0; im < 4; im++)
#pragma unroll
                for (int in = 0; in < 4; in++) {
                    asm volatile(
                        "mma.sync.aligned.m16n8k16.row.col.f32.f16.f16.f32 "
                        "{%0,%1,%2,%3},{%4,%5,%6,%7},{%8,%9},{%0,%1,%2,%3};\n"
                        : "+f"(acc[im][in][0]), "+f"(acc[im][in][1]),
                          "+f"(acc[im][in][2]), "+f"(acc[im][in][3])
                        : "r"(af[im][0]), "r"(af[im][1]), "r"(af[im][2]), "r"(af[im][3]),
                          "r"(bf[in][0]), "r"(bf[in][1]));
                }
        }
    }

    // epilogue
    const bool isv = KV && (m0 >= 512);
#pragma unroll
    for (int im = 0; im < 4; im++) {
        int r0 = m0 + wm + im * 16 + g;
        int r1 = r0 + 8;
        float bv0 = HAS_BIAS ? bias[r0] : 0.f;
        float bv1 = HAS_BIAS ? bias[r1] : 0.f;
        float w0, b0, w1, b1;
        if (RESX) {
            float2 st0 = stats[blockIdx.z * NGRP + (r0 >> 5)];
            w0 = resw[r0] * st0.y; b0 = resb[r0] - st0.x * w0;
            w1 = resw[r1] * st0.y; b1 = resb[r1] - st0.x * w1;
        }
#pragma unroll
        for (int in = 0; in < 4; in++) {
            int c0 = n0 + wn + in * 8 + 2 * t;
            float v0 = acc[im][in][0] + bv0;
            float v1 = acc[im][in][1] + bv0;
            float v2 = acc[im][in][2] + bv1;
            float v3 = acc[im][in][3] + bv1;
            if (CSCALE) {
                float2 cs = *reinterpret_cast<const float2*>(&cscale[c0]);
                v0 *= cs.x; v1 *= cs.y; v2 *= cs.x; v3 *= cs.y;
            }
            if (C_HALF || isv) {
                __half* C16 = (C_HALF ? (__half*)Cv + (size_t)blockIdx.z * sC
                                      : C2 + (size_t)blockIdx.z * sC2);
                int rr0 = isv ? r0 - 512 : r0;
                int rr1 = isv ? r1 - 512 : r1;
                *reinterpret_cast<__half2*>(&C16[(size_t)rr0 * ldc + c0]) = __floats2half2_rn(v0, v1);
                *reinterpret_cast<__half2*>(&C16[(size_t)rr1 * ldc + c0]) = __floats2half2_rn(v2, v3);
            } else {
                float* C = (float*)Cv + (size_t)blockIdx.z * sC;
                if (RESX) {
                    float2 x0 = *reinterpret_cast<const float2*>(&resx[(size_t)r0 * ldc + c0]);
                    float2 x1 = *reinterpret_cast<const float2*>(&resx[(size_t)r1 * ldc + c0]);
                    v0 += x0.x * w0 + b0; v1 += x0.y * w0 + b0;
                    v2 += x1.x * w1 + b1; v3 += x1.y * w1 + b1;
                }
                *reinterpret_cast<float2*>(&C[(size_t)r0 * ldc + c0]) = make_float2(v0, v1);
                *reinterpret_cast<float2*>(&C[(size_t)r1 * ldc + c0]) = make_float2(v2, v3);
            }
        }
    }
}

// ---------------------------------------------------------------------------
extern "C" void kernel_launch(void* const* d_in, const int* in_sizes, int n_in,
                              void* d_out, int out_size)
{
    const float* x   = (const float*)d_in[0];
    const float* n1w = (const float*)d_in[1];
    const float* n1b = (const float*)d_in[2];
    const float* kvw = (const float*)d_in[3];
    const float* kvb = (const float*)d_in[4];
    const float* n2w = (const float*)d_in[5];
    const float* n2b = (const float*)d_in[6];
    const float* ow  = (const float*)d_in[7];
    const float* ob  = (const float*)d_in[8];
    float* out = (float*)d_out;

    float *kf, *rsinv, *csinv;
    float2 *part, *stats1, *stats2;
    __half *o116, *xn16, *v16, *E16, *h16, *ctx16, *w16;
    cudaGetSymbolAddress((void**)&kf,     g_k);
    cudaGetSymbolAddress((void**)&o116,   g_o116);
    cudaGetSymbolAddress((void**)&xn16,   g_xn16);
    cudaGetSymbolAddress((void**)&v16,    g_v16);
    cudaGetSymbolAddress((void**)&E16,    g_E16);
    cudaGetSymbolAddress((void**)&h16,    g_h16);
    cudaGetSymbolAddress((void**)&ctx16,  g_ctx16);
    cudaGetSymbolAddress((void**)&rsinv,  g_rsinv);
    cudaGetSymbolAddress((void**)&csinv,  g_csinv);
    cudaGetSymbolAddress((void**)&part,   g_part);
    cudaGetSymbolAddress((void**)&stats1, g_stats1);
    cudaGetSymbolAddress((void**)&stats2, g_stats2);
    cudaGetSymbolAddress((void**)&w16,    g_w16);

    __half* kvw16 = w16;
    __half* ow16  = w16 + 1024 * 512;

    const size_t sXN  = (size_t)CCH * NSP;
    const size_t sCTX = (size_t)CCH * CCH;
    const int NBLK = BATCH * NGRP * 8;  // 2048

    // 0. weight converts
    cvt16<<<256, 256>>>(kvw, kvw16, (1024 * 512) / 4);
    cvt16<<<128, 256>>>(ow,  ow16,  (512 * 512) / 4);

    // 1. GroupNorm1 -> xn16 [c][n] fp16 + stats1
    gstats32<<<NBLK, 256>>>(x, part);
    gred<<<1, 256>>>(part, stats1);
    gnorm<float, 0><<<NBLK, 256>>>(x, n1w, n1b, stats1, xn16);

    // 2. kv GEMM (TB): k (fp32) + v16 (fp16) split. M=1024,N=4096,K=512
    gemm_fp16<true, true, false, true, false, false>
        <<<dim3(NSP / 128, 1024 / 128, BATCH), 256>>>(
        kvw16, xn16, kf, v16, kvb, nullptr, nullptr, nullptr, nullptr, nullptr, 0,
        CCH, NSP, NSP, CCH, 0, sXN, sXN, sXN);

    // 3. E = exp(k) + rowsum-inv; colsum-inv
    expk<<<BATCH * CCH, 256>>>(kf, E16, rsinv);
    colsum<<<BATCH * 8, 256>>>(E16, csinv, 0.044194173824159216f);

    // 4. ctx2[e,d] = (sum_n v[e,n]*E[d,n]) * rsinv[d]  -> fp16
    gemm_fp16<false, false, true, false, false, true>
        <<<dim3(CCH / 128, CCH / 128, BATCH), 256>>>(
        v16, E16, ctx16, nullptr, nullptr, nullptr, nullptr, nullptr, nullptr, rsinv, CCH,
        NSP, NSP, CCH, NSP, sXN, sXN, sCTX, 0);

    // 5. o1[e,n] = (sum_d ctx2[e,d]*E[d,n]) * csinv[n]  -> fp16 (TB + CSCALE)
    gemm_fp16<false, true, true, false, false, true>
        <<<dim3(NSP / 128, CCH / 128, BATCH), 256>>>(
        ctx16, E16, o116, nullptr, nullptr, nullptr, nullptr, nullptr, nullptr, csinv, NSP,
        CCH, NSP, NSP, CCH, sCTX, sXN, sXN, 0);

    // 6. h = gelu(GN2(o1)) -> h16 [c][n]
    gstats16<<<NBLK, 256>>>(o116, part);
    gred<<<1, 256>>>(part, stats2);
    gnorm<__half, 1><<<NBLK, 256>>>(o116, n2w, n2b, stats2, h16);

    // 7. out = W_out @ h + b_out + gn1(x)   (TB + RESX)
    gemm_fp16<false, true, false, true, true, false>
        <<<dim3(NSP / 128, CCH / 128, BATCH), 256>>>(
        ow16, h16, out, nullptr, ob, x, stats1, n1w, n1b, nullptr, 0,
        CCH, NSP, NSP, CCH, 0, sXN, sXN, 0);
}